// round 12
// baseline (speedup 1.0000x reference)
#include <cuda_runtime.h>
#include <cuda_bf16.h>
#include <math.h>
#include <stdint.h>

// ---------------- problem constants ----------------
#define Bn   16
#define Nn   3136        // 56*56
#define Cn   512
#define NH   8
#define HD   64
#define Fn   128         // 2*HD
#define Mrows (Bn*Nn)    // 50176
#define HW   56

// ---------------- scratch (device globals; no allocs allowed) --------------
__device__ __align__(16) float d_qgkv[Mrows * 1024];        // [b,n, (g_h|v_h) x8 heads]
__device__ __align__(16) float d_xr[Mrows * 512];           // x, tf32, FRAGMENT layout
__device__ __align__(16) __nv_bfloat16 d_qf[Bn*NH*Nn*Fn];   // q_sim  [bh,n,128] bf16
__device__ __align__(16) __nv_bfloat16 d_kf[Bn*NH*Nn*Fn];   // kf     [bh,n,128] bf16
__device__ __align__(16) float d_km[Bn*NH*Fn];              // mean over n
__device__ __align__(16) float d_kvm[Bn*NH*Fn*64];          // [bh,d(128),e(64)]
__device__ __align__(16) float d_kvm2[Bn*NH*Fn*72];         // [bh,d(128),72] B for attn
__device__ __align__(16) float d_t [Mrows * Cn];            // (xo+vd)*g, tf32, FRAGMENT layout
__device__ __align__(16) float d_wtc[2048 * 512];           // interleaved weights tf32 FRAGMENT
__device__ __align__(16) float d_wt3[512 * 512];            // proj_w^T tf32, FRAGMENT
__device__ __align__(16) float d_scinv[Cn];
__device__ __align__(16) float d_pw[Cn];

// =====================================================================
// helpers (baseline PTX only)
// =====================================================================
__device__ __forceinline__ uint32_t smem_u32(const void* p) {
    uint32_t a;
    asm("{ .reg .u64 t; cvta.to.shared.u64 t, %1; cvt.u32.u64 %0, t; }"
        : "=r"(a) : "l"(p));
    return a;
}

__device__ __forceinline__ float to_tf32(float x) {
    float r;
    asm("cvt.rna.tf32.f32 %0, %1;" : "=f"(r) : "f"(x));
    return r;
}

__device__ __forceinline__ void cp_async16(uint32_t saddr, const void* gaddr) {
    asm volatile("cp.async.ca.shared.global [%0], [%1], 16;"
                 :: "r"(saddr), "l"(gaddr) : "memory");
}
#define CP_COMMIT() asm volatile("cp.async.commit_group;" ::: "memory")
#define CP_WAIT(N)  asm volatile("cp.async.wait_group %0;" :: "n"(N) : "memory")

__device__ __forceinline__ void mma_tf32_16_8_8(float* c, const uint32_t* a,
                                                uint32_t b0, uint32_t b1) {
    asm volatile(
        "mma.sync.aligned.m16n8k8.row.col.f32.tf32.tf32.f32 "
        "{%0,%1,%2,%3}, {%4,%5,%6,%7}, {%8,%9}, {%0,%1,%2,%3};"
        : "+f"(c[0]), "+f"(c[1]), "+f"(c[2]), "+f"(c[3])
        : "r"(a[0]), "r"(a[1]), "r"(a[2]), "r"(a[3]), "r"(b0), "r"(b1));
}

__device__ __forceinline__ uint32_t bf_as_tf32(uint16_t h) {
    __nv_bfloat16 b = *reinterpret_cast<__nv_bfloat16*>(&h);
    return __float_as_uint(__bfloat162float(b));
}

// fragment-order permutation for K=512 operand panels of 128 rows.
__device__ __forceinline__ size_t perm_idx(int r, int k) {
    return (size_t)(r >> 7) * 65536
         + (size_t)((((k >> 3) * 8 + ((r >> 4) & 7)) << 7)
         + (((r & 7) * 4 + (k & 3)) << 2)
         + ((r >> 3) & 1) + (((k >> 2) & 1) << 1));
}

// =====================================================================
// tensor-core tf32 GEMM: C = A[M,512] @ Bt[panels]^T
// CTA 128x128, 4 warps (2m x 2n), warp 64x64, 2 CTAs/SM, 3-stage.
// mode 0: plain + bias -> Cm (gemm3)
// mode 1: fused epilogues:
//   bn_panel < 8 : [q_h | k_h] tile -> feature transform -> d_qf/d_kf bf16
//   bn_panel >= 8: [g_h | v_h] tile -> d_qgkv (stride 1024)
// =====================================================================
#define GEMM_SMEM (3 * 8192 * 4)       // 98304 B

__global__ __launch_bounds__(128, 2)
void gemm_mma(const float* __restrict__ A, const float* __restrict__ Bt,
              const float* __restrict__ bias, float* __restrict__ Cm, int Nc,
              int mode, const float* __restrict__ pos_enc)
{
    extern __shared__ float sm[];
    float* stage[3] = { sm, sm + 8192, sm + 16384 };
    const int tid = threadIdx.x;
    const int bn_panel = blockIdx.x;
    const int bm_panel = blockIdx.y;
    const int wid = tid >> 5, lane = tid & 31;
    const int lr = lane >> 2, lc = lane & 3;
    const int wmg = (wid & 1) * 4;
    const int wng = (wid >> 1) * 4;

    const float* Ab = A  + (size_t)bm_panel * 65536;
    const float* Bb = Bt + (size_t)bn_panel * 65536;

    float c[4][8][4];
#pragma unroll
    for (int mt = 0; mt < 4; mt++)
#pragma unroll
        for (int nt = 0; nt < 8; nt++)
#pragma unroll
            for (int j = 0; j < 4; j++) c[mt][nt][j] = 0.f;

    auto issue_stage = [&](int buf, int t) {
        uint32_t sa = smem_u32(stage[buf]);
        const float* as = Ab + t * 4096;
        const float* bs = Bb + t * 4096;
#pragma unroll
        for (int i = 0; i < 8; i++) {
            int ch = tid + i * 128;
            cp_async16(sa + ch * 16, as + ch * 4);
        }
#pragma unroll
        for (int i = 0; i < 8; i++) {
            int ch = tid + i * 128;
            cp_async16(sa + 16384 + ch * 16, bs + ch * 4);
        }
        CP_COMMIT();
    };

    issue_stage(0, 0);
    issue_stage(1, 1);

    for (int t = 0; t < 16; t++) {
        CP_WAIT(1);
        __syncthreads();
        if (t + 2 < 16) issue_stage((t + 2) % 3, t + 2);
        else            CP_COMMIT();

        const float4* sa4 = (const float4*)stage[t % 3];
        const float4* sb4 = (const float4*)(stage[t % 3] + 4096);
#pragma unroll
        for (int kk = 0; kk < 4; kk++) {
            uint32_t a[4][4];
            float4 bv[4];
#pragma unroll
            for (int mt = 0; mt < 4; mt++) {
                float4 v = sa4[(kk * 8 + wmg + mt) * 32 + lane];
                a[mt][0] = __float_as_uint(v.x);
                a[mt][1] = __float_as_uint(v.y);
                a[mt][2] = __float_as_uint(v.z);
                a[mt][3] = __float_as_uint(v.w);
            }
#pragma unroll
            for (int p = 0; p < 4; p++)
                bv[p] = sb4[(kk * 8 + wng + p) * 32 + lane];
#pragma unroll
            for (int mt = 0; mt < 4; mt++)
#pragma unroll
                for (int p = 0; p < 4; p++) {
                    mma_tf32_16_8_8(c[mt][2 * p],
                                    a[mt], __float_as_uint(bv[p].x),
                                           __float_as_uint(bv[p].z));
                    mma_tf32_16_8_8(c[mt][2 * p + 1],
                                    a[mt], __float_as_uint(bv[p].y),
                                           __float_as_uint(bv[p].w));
                }
        }
    }

    if (mode == 0) {
        // plain + bias epilogue (gemm3 -> out)
#pragma unroll
        for (int mt = 0; mt < 4; mt++) {
            int row = bm_panel * 128 + (wid & 1) * 64 + mt * 16 + lr;
#pragma unroll
            for (int nt = 0; nt < 8; nt++) {
                int col = bn_panel * 128 + (wid >> 1) * 64 + nt * 8 + lc * 2;
                float2 v0 = make_float2(c[mt][nt][0], c[mt][nt][1]);
                float2 v1 = make_float2(c[mt][nt][2], c[mt][nt][3]);
                float b0 = bias[col], b1 = bias[col + 1];
                v0.x += b0; v0.y += b1;
                v1.x += b0; v1.y += b1;
                *(float2*)&Cm[(size_t)row * Nc + col] = v0;
                *(float2*)&Cm[(size_t)(row + 8) * Nc + col] = v1;
            }
        }
    } else if (bn_panel < 8) {
        // fused feature epilogue: warps 0,1 hold q_h; warps 2,3 hold k_h
        const int h = bn_panel;
        const bool isq = (wid >> 1) == 0;
        __nv_bfloat16* dst = isq ? d_qf : d_kf;
#pragma unroll
        for (int mt = 0; mt < 4; mt++) {
#pragma unroll
            for (int rh = 0; rh < 2; rh++) {
                int row = bm_panel * 128 + (wid & 1) * 64 + mt * 16 + lr + rh * 8;
                int b = row / Nn;
                int n = row - b * Nn;
                size_t fbase = ((size_t)(b * NH + h) * Nn + n) << 7;
#pragma unroll
                for (int nt = 0; nt < 8; nt++) {
                    int d0 = nt * 8 + lc * 2;
                    int c0 = h * 64 + d0;
                    float v0 = c[mt][nt][rh * 2 + 0];
                    float v1 = c[mt][nt][rh * 2 + 1];
                    if (!isq) {
                        v0 += pos_enc[n * Cn + c0];
                        v1 += pos_enc[n * Cn + c0 + 1];
                    }
                    v0 *= d_scinv[c0];
                    v1 *= d_scinv[c0 + 1];
                    float a0 = exp2f(d_pw[c0]     * __log2f(fabsf(v0)));
                    float a1 = exp2f(d_pw[c0 + 1] * __log2f(fabsf(v1)));
                    float pp0 = (v0 > 0.f) ? a0 : 0.f;
                    float pn0 = (v0 < 0.f) ? a0 : 0.f;
                    float pp1 = (v1 > 0.f) ? a1 : 0.f;
                    float pn1 = (v1 < 0.f) ? a1 : 0.f;
                    *(__nv_bfloat162*)&dst[fbase + d0] =
                        __floats2bfloat162_rn(pp0, pp1);
                    *(__nv_bfloat162*)&dst[fbase + 64 + d0] =
                        __floats2bfloat162_rn(pn0, pn1);
                }
            }
        }
    } else {
        // g|v panel -> d_qgkv [row][1024], head h: g at h*128, v at h*128+64
        int colbase = (bn_panel - 8) * 128 + (wid >> 1) * 64;
#pragma unroll
        for (int mt = 0; mt < 4; mt++) {
            int row = bm_panel * 128 + (wid & 1) * 64 + mt * 16 + lr;
#pragma unroll
            for (int nt = 0; nt < 8; nt++) {
                int col = colbase + nt * 8 + lc * 2;
                *(float2*)&d_qgkv[(size_t)row * 1024 + col] =
                    make_float2(c[mt][nt][0], c[mt][nt][1]);
                *(float2*)&d_qgkv[(size_t)(row + 8) * 1024 + col] =
                    make_float2(c[mt][nt][2], c[mt][nt][3]);
            }
        }
    }
}

// =====================================================================
// interleaved weight transpose: out col j (0..2047):
// panel p=j>>7, h=p&7, o=j&127: p<8: o<64 -> qg[:,h*64+o], else kv[:,h*64+(o-64)]
//                               p>=8: o<64 -> qg[:,512+h*64+o], else kv[:,512+...]
// =====================================================================
__global__ void transpose_qgkv(const float* __restrict__ qg_w,
                               const float* __restrict__ kv_w)
{
    __shared__ float t[32][33];
    int bx = blockIdx.x * 32;     // 32-col blocks stay within one (p, o-half)
    int by = blockIdx.y * 32;
    int x = threadIdx.x, y = threadIdx.y;
    int p = bx >> 7;
    int o = bx & 127;
    int h = p & 7;
    const float* W = (o < 64) ? qg_w : kv_w;
    int src0 = ((p < 8) ? 0 : 512) + h * 64 + (o & 63);
#pragma unroll
    for (int j = 0; j < 32; j += 8)
        t[y + j][x] = W[(size_t)(by + y + j) * 1024 + src0 + x];
    __syncthreads();
#pragma unroll
    for (int j = 0; j < 32; j += 8)
        d_wtc[perm_idx(bx + y + j, by + x)] = to_tf32(t[x][y + j]);
}

__global__ void transpose_w(const float* __restrict__ W, float* __restrict__ Wt, int Nc)
{
    __shared__ float t[32][33];
    int bx = blockIdx.x * 32;
    int by = blockIdx.y * 32;
    int x = threadIdx.x, y = threadIdx.y;
#pragma unroll
    for (int j = 0; j < 32; j += 8)
        t[y + j][x] = W[(size_t)(by + y + j) * Nc + bx + x];
    __syncthreads();
#pragma unroll
    for (int j = 0; j < 32; j += 8)
        Wt[perm_idx(bx + y + j, by + x)] = to_tf32(t[x][y + j]);
}

// =====================================================================
// x -> tf32 fragment layout
// =====================================================================
__global__ void permute_x(const float* __restrict__ x)
{
    int idx = blockIdx.x * 256 + threadIdx.x;
    int r = idx >> 7;
    int k = (idx & 127) * 4;
    float4 v = ((const float4*)x)[idx];
    size_t base = perm_idx(r, k);
    d_xr[base]      = to_tf32(v.x);
    d_xr[base + 4]  = to_tf32(v.y);
    d_xr[base + 8]  = to_tf32(v.z);
    d_xr[base + 12] = to_tf32(v.w);
}

// =====================================================================
// per-channel params
// =====================================================================
__global__ void prep_params(const float* __restrict__ scale_p,
                            const float* __restrict__ power_p)
{
    int c = threadIdx.x;
    d_scinv[c] = 1.f / log1pf(expf(scale_p[c]));
    d_pw[c] = 1.f + 4.f / (1.f + expf(-power_p[c]));
}

// =====================================================================
// km = mean over n of kf (bf16 read)
// =====================================================================
__global__ void km_kernel()
{
    int bh  = blockIdx.x;
    int seg = blockIdx.y;
    int f   = threadIdx.x;     // 0..127
    const __nv_bfloat16* src =
        &d_kf[((size_t)bh * Nn + seg * (Nn / 8)) * Fn + f];
    float s = 0.f;
    for (int i = 0; i < Nn / 8; i++)
        s += __bfloat162float(src[(size_t)i * Fn]);
    atomicAdd(&d_km[bh * Fn + f], s * (1.f / (float)Nn));
}

// =====================================================================
// kvm via mma (4 segments); v at d_qgkv[row*1024 + h*128 + 64 + e]
// =====================================================================
#define KV_SEG 784

__global__ __launch_bounds__(256)
void kvm_mma()
{
    __shared__ __align__(16) uint16_t kfs[2][32][136];
    __shared__ __align__(16) float    vss[2][32][72];
    int bh = blockIdx.x, seg = blockIdx.y;
    int b = bh >> 3, h = bh & 7;
    int tid = threadIdx.x, wid = tid >> 5, lane = tid & 31;
    int lr = lane >> 2, lc = lane & 3;
    int wd = (wid & 1) * 64;
    int we = (wid >> 1) * 16;

    float c[4][2][4];
#pragma unroll
    for (int mt = 0; mt < 4; mt++)
#pragma unroll
        for (int nt = 0; nt < 2; nt++)
#pragma unroll
            for (int j = 0; j < 4; j++) c[mt][nt][j] = 0.f;

    int nbase = seg * KV_SEG;
    const int voff = h * 128 + 64;
#pragma unroll
    for (int j = 0; j < 2; j++) {
        int idx = tid + j * 256;
        int r = idx >> 4, cs = idx & 15;
        cp_async16(smem_u32(&kfs[0][r][cs * 8]),
                   &d_kf[((size_t)bh * Nn + nbase + r) * 128 + cs * 8]);
        cp_async16(smem_u32(&vss[0][r][cs * 4]),
                   &d_qgkv[((size_t)(b * Nn) + nbase + r) * 1024 + voff + cs * 4]);
    }
    CP_COMMIT();

    const int NT = 25;    // 24 full 32-row tiles + 16-row tail
    for (int t = 0; t < NT; t++) {
        if (t + 1 < NT) {
            int nb = (t + 1) & 1;
            int n0 = nbase + (t + 1) * 32;
            int rows = (t + 1 == NT - 1) ? 16 : 32;
#pragma unroll
            for (int j = 0; j < 2; j++) {
                int idx = tid + j * 256;
                int r = idx >> 4, cs = idx & 15;
                if (r < rows) {
                    cp_async16(smem_u32(&kfs[nb][r][cs * 8]),
                               &d_kf[((size_t)bh * Nn + n0 + r) * 128 + cs * 8]);
                    cp_async16(smem_u32(&vss[nb][r][cs * 4]),
                               &d_qgkv[((size_t)(b * Nn) + n0 + r) * 1024 + voff + cs * 4]);
                } else {
                    *(float4*)((char*)&kfs[nb][r][cs * 8]) = make_float4(0.f, 0.f, 0.f, 0.f);
                    *(float4*)&vss[nb][r][cs * 4] = make_float4(0.f, 0.f, 0.f, 0.f);
                }
            }
            CP_COMMIT();
            CP_WAIT(1);
        } else {
            CP_WAIT(0);
        }
        __syncthreads();
        int buf = t & 1;
#pragma unroll
        for (int kk = 0; kk < 4; kk++) {
            int k0 = kk * 8;
            uint32_t a[4][4];
#pragma unroll
            for (int mt = 0; mt < 4; mt++) {
                int db = wd + mt * 16;
                a[mt][0] = bf_as_tf32(kfs[buf][k0 + lc][db + lr]);
                a[mt][1] = bf_as_tf32(kfs[buf][k0 + lc][db + lr + 8]);
                a[mt][2] = bf_as_tf32(kfs[buf][k0 + lc + 4][db + lr]);
                a[mt][3] = bf_as_tf32(kfs[buf][k0 + lc + 4][db + lr + 8]);
            }
#pragma unroll
            for (int nt = 0; nt < 2; nt++) {
                int eb = we + nt * 8;
                uint32_t b0 = __float_as_uint(vss[buf][k0 + lc][eb + lr]);
                uint32_t b1 = __float_as_uint(vss[buf][k0 + lc + 4][eb + lr]);
#pragma unroll
                for (int mt = 0; mt < 4; mt++)
                    mma_tf32_16_8_8(c[mt][nt], a[mt], b0, b1);
            }
        }
        __syncthreads();
    }

    const float inv_n = 1.f / (float)Nn;
    float* dst = &d_kvm[(size_t)bh * 8192];
#pragma unroll
    for (int mt = 0; mt < 4; mt++) {
        int d0 = wd + mt * 16 + lr;
#pragma unroll
        for (int nt = 0; nt < 2; nt++) {
            int e0 = we + nt * 8 + 2 * lc;
            atomicAdd(&dst[d0 * 64 + e0],           c[mt][nt][0] * inv_n);
            atomicAdd(&dst[d0 * 64 + e0 + 1],       c[mt][nt][1] * inv_n);
            atomicAdd(&dst[(d0 + 8) * 64 + e0],     c[mt][nt][2] * inv_n);
            atomicAdd(&dst[(d0 + 8) * 64 + e0 + 1], c[mt][nt][3] * inv_n);
        }
    }
}

// =====================================================================
// build KVM2
// =====================================================================
__global__ void build_kvm2()
{
    int bh = blockIdx.x;
    const float* kvm = &d_kvm[(size_t)bh * 8192];
    const float* km  = &d_km[bh * 128];
    float* out = &d_kvm2[(size_t)bh * 9216];
    for (int i = threadIdx.x; i < 128 * 72; i += 256) {
        int dd = i / 72, col = i - dd * 72;
        float v;
        if (col < 32)       v = kvm[dd * 64 + col];
        else if (col < 64)  v = kvm[(dd ^ 64) * 64 + col];
        else if (col == 64) v = km[dd];
        else if (col == 65) v = km[dd ^ 64];
        else                v = 0.f;
        out[i] = v;
    }
}

// =====================================================================
// attention via mma; scatter-stores d_t in FRAGMENT layout
// =====================================================================
#define ATT_SMEM (36864 + 17408)

__global__ __launch_bounds__(128)
void attn_mma()
{
    extern __shared__ char smx[];
    float*    Bsm = (float*)smx;
    uint16_t* Asm = (uint16_t*)(smx + 36864);
    int m0 = blockIdx.x * 64, bh = blockIdx.y;
    int b = bh >> 3, h = bh & 7;
    int tid = threadIdx.x, wid = tid >> 5, lane = tid & 31;
    int lr = lane >> 2, lc = lane & 3;
    int wm = wid * 16;

    {
        const char* bsrc = (const char*)&d_kvm2[(size_t)bh * 9216];
#pragma unroll
        for (int j = 0; j < 18; j++) {
            int idx = tid + j * 128;
            cp_async16(smem_u32((char*)Bsm + idx * 16), bsrc + idx * 16);
        }
#pragma unroll
        for (int j = 0; j < 8; j++) {
            int idx = tid + j * 128;
            int r = idx >> 4, cs = idx & 15;
            cp_async16(smem_u32(&Asm[r * 136 + cs * 8]),
                       &d_qf[((size_t)bh * Nn + m0 + r) * 128 + cs * 8]);
        }
        CP_COMMIT(); CP_WAIT(0);
    }
    __syncthreads();

    float c[9][4];
#pragma unroll
    for (int nt = 0; nt < 9; nt++)
#pragma unroll
        for (int j = 0; j < 4; j++) c[nt][j] = 0.f;

#pragma unroll
    for (int kt = 0; kt < 16; kt++) {
        int k0 = kt * 8;
        uint32_t a[4];
        a[0] = bf_as_tf32(Asm[(wm + lr) * 136 + k0 + lc]);
        a[1] = bf_as_tf32(Asm[(wm + lr + 8) * 136 + k0 + lc]);
        a[2] = bf_as_tf32(Asm[(wm + lr) * 136 + k0 + lc + 4]);
        a[3] = bf_as_tf32(Asm[(wm + lr + 8) * 136 + k0 + lc + 4]);
#pragma unroll
        for (int nt = 0; nt < 9; nt++) {
            uint32_t b0 = __float_as_uint(Bsm[(k0 + lc) * 72 + nt * 8 + lr]);
            uint32_t b1 = __float_as_uint(Bsm[(k0 + lc + 4) * 72 + nt * 8 + lr]);
            mma_tf32_16_8_8(c[nt], a, b0, b1);
        }
    }

    int src = lane & 28;
    float den1a = __shfl_sync(0xffffffffu, c[8][0], src);
    float den2a = __shfl_sync(0xffffffffu, c[8][1], src);
    float den1b = __shfl_sync(0xffffffffu, c[8][2], src);
    float den2b = __shfl_sync(0xffffffffu, c[8][3], src);
    float z1a = 1.f / (den1a + 1e-6f), z2a = 1.f / (den2a + 1e-6f);
    float z1b = 1.f / (den1b + 1e-6f), z2b = 1.f / (den2b + 1e-6f);

    int ra = b * Nn + m0 + wm + lr;
    int rb = ra + 8;
#pragma unroll
    for (int nt = 0; nt < 8; nt++) {
        int col = nt * 8 + 2 * lc;
        float za = (col < 32) ? z1a : z2a;
        float zb = (col < 32) ? z1b : z2b;
        int k = h * 64 + col;
        d_t[perm_idx(ra, k)]     = c[nt][0] * za;
        d_t[perm_idx(ra, k + 1)] = c[nt][1] * za;
        d_t[perm_idx(rb, k)]     = c[nt][2] * zb;
        d_t[perm_idx(rb, k + 1)] = c[nt][3] * zb;
    }
}

// =====================================================================
// depthwise conv + gate; g|v layout (stride 1024); d_t fragment RMW
// =====================================================================
__global__ __launch_bounds__(512)
void conv_gate_kernel(const float* __restrict__ dwc_w,
                      const float* __restrict__ dwc_b)
{
    __shared__ float ws[64 * 25];
    __shared__ float bs[64];
    int y = blockIdx.x;
    int b = blockIdx.y;
    int c = threadIdx.x;
    int d = c & 63;
    int h = c >> 6;
    for (int i = c; i < 64 * 25; i += 512) ws[i] = dwc_w[i];
    if (c < 64) bs[c] = dwc_b[c];
    __syncthreads();

    const float* vbase = &d_qgkv[(size_t)(b * Nn) * 1024 + h * 128 + 64 + d];
    const float* gbase = &d_qgkv[(size_t)(b * Nn) * 1024 + h * 128 + d];

    float win[5][5];
#pragma unroll
    for (int dy = 0; dy < 5; dy++) {
        int yy = y + dy - 2;
        bool yok = (unsigned)yy < HW;
#pragma unroll
        for (int j = 0; j < 5; j++) {
            int xx = j - 2;
            win[dy][j] = (yok && (unsigned)xx < HW)
                         ? vbase[(size_t)(yy * HW + xx) * 1024] : 0.f;
        }
    }

    for (int x = 0; x < HW; x++) {
        float acc = bs[d];
#pragma unroll
        for (int dy = 0; dy < 5; dy++)
#pragma unroll
            for (int j = 0; j < 5; j++)
                acc = fmaf(win[dy][j], ws[d * 25 + dy * 5 + j], acc);

        int i1 = b * Nn + y * HW + x;
        float g = gbase[(size_t)(y * HW + x) * 1024];
        size_t pi = perm_idx(i1, c);
        d_t[pi] = to_tf32((d_t[pi] + acc) * g);

        int xx = x + 3;
        bool xok = xx < HW;
#pragma unroll
        for (int dy = 0; dy < 5; dy++) {
#pragma unroll
            for (int j = 0; j < 4; j++) win[dy][j] = win[dy][j + 1];
            int yy = y + dy - 2;
            win[dy][4] = (xok && (unsigned)yy < HW)
                         ? vbase[(size_t)(yy * HW + xx) * 1024] : 0.f;
        }
    }
}

// =====================================================================
// launch (launch #3 == big gemm for ncu capture)
// =====================================================================
extern "C" void kernel_launch(void* const* d_in, const int* in_sizes, int n_in,
                              void* d_out, int out_size)
{
    const float* x       = (const float*)d_in[0];
    const float* qg_w    = (const float*)d_in[1];
    const float* kv_w    = (const float*)d_in[2];
    const float* proj_w  = (const float*)d_in[3];
    const float* proj_b  = (const float*)d_in[4];
    const float* pos_enc = (const float*)d_in[5];
    const float* scale_p = (const float*)d_in[6];
    const float* power_p = (const float*)d_in[7];
    const float* dwc_w   = (const float*)d_in[8];
    const float* dwc_b   = (const float*)d_in[9];
    float* out = (float*)d_out;

    float *p_t, *p_wtc, *p_wt3, *p_xr, *p_km, *p_kvm;
    cudaGetSymbolAddress((void**)&p_t,    d_t);
    cudaGetSymbolAddress((void**)&p_wtc,  d_wtc);
    cudaGetSymbolAddress((void**)&p_wt3,  d_wt3);
    cudaGetSymbolAddress((void**)&p_xr,   d_xr);
    cudaGetSymbolAddress((void**)&p_km,   d_km);
    cudaGetSymbolAddress((void**)&p_kvm,  d_kvm);

    cudaFuncSetAttribute(gemm_mma, cudaFuncAttributeMaxDynamicSharedMemorySize,
                         GEMM_SMEM);
    cudaFuncSetAttribute(attn_mma, cudaFuncAttributeMaxDynamicSharedMemorySize,
                         ATT_SMEM);

    // zero accumulators (memset nodes; do not shift kernel launch indices)
    cudaMemsetAsync(p_km,  0, Bn * NH * Fn * sizeof(float));
    cudaMemsetAsync(p_kvm, 0, Bn * NH * Fn * 64 * sizeof(float));

    dim3 tb(32, 8);
    prep_params<<<1, 512>>>(scale_p, power_p);                       // 0
    permute_x<<<Mrows * 128 / 256, 256>>>(x);                        // 1
    transpose_qgkv<<<dim3(64, 16), tb>>>(qg_w, kv_w);                // 2
    gemm_mma<<<dim3(16, Mrows / 128), 128, GEMM_SMEM>>>(             // 3 (profiled)
        p_xr, p_wtc, nullptr, nullptr, 1024, 1, pos_enc);
    transpose_w<<<dim3(16, 16), tb>>>(proj_w, p_wt3, 512);           // 4
    km_kernel<<<dim3(Bn * NH, 8), Fn>>>();                           // 5
    kvm_mma<<<dim3(Bn * NH, 4), 256>>>();                            // 6
    build_kvm2<<<Bn * NH, 256>>>();                                  // 7
    attn_mma<<<dim3(Nn / 64, Bn * NH), 128, ATT_SMEM>>>();           // 8
    conv_gate_kernel<<<dim3(HW, Bn), 512>>>(dwc_w, dwc_b);           // 9
    gemm_mma<<<dim3(4, Mrows / 128), 128, GEMM_SMEM>>>(              // 10
        p_t, p_wt3, proj_b, out, 512, 0, nullptr);
}

// round 13
// speedup vs baseline: 1.6059x; 1.6059x over previous
#include <cuda_runtime.h>
#include <cuda_bf16.h>
#include <cuda_fp16.h>
#include <math.h>
#include <stdint.h>

// ---------------- problem constants ----------------
#define Bn   16
#define Nn   3136        // 56*56
#define Cn   512
#define NH   8
#define HD   64
#define Fn   128         // 2*HD
#define Mrows (Bn*Nn)    // 50176
#define HW   56

// ---------------- scratch (device globals; no allocs allowed) --------------
__device__ __align__(16) float d_qgkv[Mrows * 1024];        // [b,n, (g_h|v_h) x8 heads]
__device__ __align__(16) __half d_xr[Mrows * 512];          // x fp16, A-FRAGMENT layout
__device__ __align__(16) __nv_bfloat16 d_qf[Bn*NH*Nn*Fn];   // q_sim  [bh,n,128] bf16
__device__ __align__(16) __nv_bfloat16 d_kf[Bn*NH*Nn*Fn];   // kf     [bh,n,128] bf16
__device__ __align__(16) float d_km[Bn*NH*Fn];              // mean over n
__device__ __align__(16) float d_kvm[Bn*NH*Fn*64];          // [bh,d(128),e(64)]
__device__ __align__(16) float d_kvm2[Bn*NH*Fn*72];         // [bh,d(128),72] B for attn
__device__ __align__(16) __half d_t [Mrows * Cn];           // (xo+vd)*g fp16, A-FRAGMENT
__device__ __align__(16) __half d_wtc[2048 * 512];          // interleaved weights fp16 B-FRAG
__device__ __align__(16) __half d_wt3[512 * 512];           // proj_w^T fp16 B-FRAG
__device__ __align__(16) float d_scinv[Cn];
__device__ __align__(16) float d_pw[Cn];

// =====================================================================
// helpers (baseline PTX only)
// =====================================================================
__device__ __forceinline__ uint32_t smem_u32(const void* p) {
    uint32_t a;
    asm("{ .reg .u64 t; cvta.to.shared.u64 t, %1; cvt.u32.u64 %0, t; }"
        : "=r"(a) : "l"(p));
    return a;
}

__device__ __forceinline__ void cp_async16(uint32_t saddr, const void* gaddr) {
    asm volatile("cp.async.ca.shared.global [%0], [%1], 16;"
                 :: "r"(saddr), "l"(gaddr) : "memory");
}
#define CP_COMMIT() asm volatile("cp.async.commit_group;" ::: "memory")
#define CP_WAIT(N)  asm volatile("cp.async.wait_group %0;" :: "n"(N) : "memory")

__device__ __forceinline__ void mma_f16(float* c, const uint32_t* a,
                                        uint32_t b0, uint32_t b1) {
    asm volatile(
        "mma.sync.aligned.m16n8k16.row.col.f32.f16.f16.f32 "
        "{%0,%1,%2,%3}, {%4,%5,%6,%7}, {%8,%9}, {%0,%1,%2,%3};"
        : "+f"(c[0]), "+f"(c[1]), "+f"(c[2]), "+f"(c[3])
        : "r"(a[0]), "r"(a[1]), "r"(a[2]), "r"(a[3]), "r"(b0), "r"(b1));
}

__device__ __forceinline__ void mma_tf32_16_8_8(float* c, const uint32_t* a,
                                                uint32_t b0, uint32_t b1) {
    asm volatile(
        "mma.sync.aligned.m16n8k8.row.col.f32.tf32.tf32.f32 "
        "{%0,%1,%2,%3}, {%4,%5,%6,%7}, {%8,%9}, {%0,%1,%2,%3};"
        : "+f"(c[0]), "+f"(c[1]), "+f"(c[2]), "+f"(c[3])
        : "r"(a[0]), "r"(a[1]), "r"(a[2]), "r"(a[3]), "r"(b0), "r"(b1));
}

__device__ __forceinline__ uint32_t bf_as_tf32(uint16_t h) {
    __nv_bfloat16 b = *reinterpret_cast<__nv_bfloat16*>(&h);
    return __float_as_uint(__bfloat162float(b));
}

// A-operand fp16 fragment layout: panels of 128 rows x 512 k (in halves).
// One LDS.128 per lane per (row-group, k16) = full m16k16 A fragment.
__device__ __forceinline__ size_t perm_h(int r, int k) {
    return (size_t)(r >> 7) * 65536
         + (size_t)((((k >> 4) * 8 + ((r >> 4) & 7)) << 8)
         + (((r & 7) * 4 + ((k >> 1) & 3)) << 3)
         + ((((r >> 3) & 1) + (((k >> 3) & 1) << 1)) << 1)
         + (k & 1));
}

// B-operand fp16 fragment layout: one LDS.128 per lane per (16-col pair, k16)
// = two n8k16 B fragments [b0(even),b1(even),b0(odd),b1(odd)].
__device__ __forceinline__ size_t perm_hb(int n, int k) {
    return (size_t)(n >> 7) * 65536
         + (size_t)((((k >> 4) * 8 + ((n >> 4) & 7)) << 8)
         + (((n & 7) * 4 + ((k >> 1) & 3)) << 3)
         + ((((((n >> 3) & 1) << 1) + ((k >> 3) & 1))) << 1)
         + (k & 1));
}

// =====================================================================
// fp16 tensor-core GEMM: C = A[M,512] @ Bt^T, CTA 128x128, 4 warps,
// warp 64x64, 2 CTAs/SM, 3-stage cp.async.
// mode 0: plain + bias -> Cm (fp32 out)
// mode 1: bn_panel<8: feature epilogue -> d_qf/d_kf; else g|v -> d_qgkv
// =====================================================================
#define GEMM_SMEM (3 * 16384)      // 3 stages x 16KB = 49152 B

__global__ __launch_bounds__(128, 2)
void gemm_mma(const __half* __restrict__ A, const __half* __restrict__ Bt,
              const float* __restrict__ bias, float* __restrict__ Cm, int Nc,
              int mode, const float* __restrict__ pos_enc)
{
    extern __shared__ __half smh[];
    __half* stage[3] = { smh, smh + 8192, smh + 16384 };
    const int tid = threadIdx.x;
    const int bn_panel = blockIdx.x;
    const int bm_panel = blockIdx.y;
    const int wid = tid >> 5, lane = tid & 31;
    const int lr = lane >> 2, lc = lane & 3;
    const int wmg = (wid & 1) * 4;       // A row-group base
    const int wnp = (wid >> 1) * 4;      // B pair base

    const __half* Ab = A  + (size_t)bm_panel * 65536;
    const __half* Bb = Bt + (size_t)bn_panel * 65536;

    float c[4][8][4];
#pragma unroll
    for (int mt = 0; mt < 4; mt++)
#pragma unroll
        for (int nt = 0; nt < 8; nt++)
#pragma unroll
            for (int j = 0; j < 4; j++) c[mt][nt][j] = 0.f;

    auto issue_stage = [&](int buf, int t) {
        uint32_t sa = smem_u32(stage[buf]);
        const __half* as = Ab + t * 4096;
        const __half* bs = Bb + t * 4096;
#pragma unroll
        for (int i = 0; i < 4; i++) {
            int ch = tid + i * 128;
            cp_async16(sa + ch * 16, as + ch * 8);
        }
#pragma unroll
        for (int i = 0; i < 4; i++) {
            int ch = tid + i * 128;
            cp_async16(sa + 8192 + ch * 16, bs + ch * 8);
        }
        CP_COMMIT();
    };

    issue_stage(0, 0);
    issue_stage(1, 1);

    for (int t = 0; t < 16; t++) {
        CP_WAIT(1);
        __syncthreads();
        if (t + 2 < 16) issue_stage((t + 2) % 3, t + 2);
        else            CP_COMMIT();

        const uint4* sa4 = (const uint4*)stage[t % 3];
        const uint4* sb4 = (const uint4*)(stage[t % 3] + 4096);
#pragma unroll
        for (int kk = 0; kk < 2; kk++) {
            uint4 av[4], bv[4];
#pragma unroll
            for (int mt = 0; mt < 4; mt++)
                av[mt] = sa4[(kk * 8 + wmg + mt) * 32 + lane];
#pragma unroll
            for (int j = 0; j < 4; j++)
                bv[j] = sb4[(kk * 8 + wnp + j) * 32 + lane];
#pragma unroll
            for (int mt = 0; mt < 4; mt++) {
                uint32_t a[4] = { av[mt].x, av[mt].y, av[mt].z, av[mt].w };
#pragma unroll
                for (int j = 0; j < 4; j++) {
                    mma_f16(c[mt][2 * j],     a, bv[j].x, bv[j].y);
                    mma_f16(c[mt][2 * j + 1], a, bv[j].z, bv[j].w);
                }
            }
        }
    }

    if (mode == 0) {
#pragma unroll
        for (int mt = 0; mt < 4; mt++) {
            int row = bm_panel * 128 + (wid & 1) * 64 + mt * 16 + lr;
#pragma unroll
            for (int nt = 0; nt < 8; nt++) {
                int col = bn_panel * 128 + (wid >> 1) * 64 + nt * 8 + lc * 2;
                float2 v0 = make_float2(c[mt][nt][0], c[mt][nt][1]);
                float2 v1 = make_float2(c[mt][nt][2], c[mt][nt][3]);
                float b0 = bias[col], b1 = bias[col + 1];
                v0.x += b0; v0.y += b1;
                v1.x += b0; v1.y += b1;
                *(float2*)&Cm[(size_t)row * Nc + col] = v0;
                *(float2*)&Cm[(size_t)(row + 8) * Nc + col] = v1;
            }
        }
    } else if (bn_panel < 8) {
        // feature epilogue: warps 0,1 -> q_h ; warps 2,3 -> k_h
        const int h = bn_panel;
        const bool isq = (wid >> 1) == 0;
        __nv_bfloat16* dst = isq ? d_qf : d_kf;
#pragma unroll
        for (int mt = 0; mt < 4; mt++) {
#pragma unroll
            for (int rh = 0; rh < 2; rh++) {
                int row = bm_panel * 128 + (wid & 1) * 64 + mt * 16 + lr + rh * 8;
                int b = row / Nn;
                int n = row - b * Nn;
                size_t fbase = ((size_t)(b * NH + h) * Nn + n) << 7;
#pragma unroll
                for (int nt = 0; nt < 8; nt++) {
                    int d0 = nt * 8 + lc * 2;
                    int c0 = h * 64 + d0;
                    float v0 = c[mt][nt][rh * 2 + 0];
                    float v1 = c[mt][nt][rh * 2 + 1];
                    if (!isq) {
                        v0 += pos_enc[n * Cn + c0];
                        v1 += pos_enc[n * Cn + c0 + 1];
                    }
                    v0 *= d_scinv[c0];
                    v1 *= d_scinv[c0 + 1];
                    float a0 = exp2f(d_pw[c0]     * __log2f(fabsf(v0)));
                    float a1 = exp2f(d_pw[c0 + 1] * __log2f(fabsf(v1)));
                    float pp0 = (v0 > 0.f) ? a0 : 0.f;
                    float pn0 = (v0 < 0.f) ? a0 : 0.f;
                    float pp1 = (v1 > 0.f) ? a1 : 0.f;
                    float pn1 = (v1 < 0.f) ? a1 : 0.f;
                    *(__nv_bfloat162*)&dst[fbase + d0] =
                        __floats2bfloat162_rn(pp0, pp1);
                    *(__nv_bfloat162*)&dst[fbase + 64 + d0] =
                        __floats2bfloat162_rn(pn0, pn1);
                }
            }
        }
    } else {
        int colbase = (bn_panel - 8) * 128 + (wid >> 1) * 64;
#pragma unroll
        for (int mt = 0; mt < 4; mt++) {
            int row = bm_panel * 128 + (wid & 1) * 64 + mt * 16 + lr;
#pragma unroll
            for (int nt = 0; nt < 8; nt++) {
                int col = colbase + nt * 8 + lc * 2;
                *(float2*)&d_qgkv[(size_t)row * 1024 + col] =
                    make_float2(c[mt][nt][0], c[mt][nt][1]);
                *(float2*)&d_qgkv[(size_t)(row + 8) * 1024 + col] =
                    make_float2(c[mt][nt][2], c[mt][nt][3]);
            }
        }
    }
}

// =====================================================================
// interleaved weight transpose -> fp16 B-fragment layout
// =====================================================================
__global__ void transpose_qgkv(const float* __restrict__ qg_w,
                               const float* __restrict__ kv_w)
{
    __shared__ float t[32][33];
    int bx = blockIdx.x * 32;
    int by = blockIdx.y * 32;
    int x = threadIdx.x, y = threadIdx.y;
    int p = bx >> 7;
    int o = bx & 127;
    int h = p & 7;
    const float* W = (o < 64) ? qg_w : kv_w;
    int src0 = ((p < 8) ? 0 : 512) + h * 64 + (o & 63);
#pragma unroll
    for (int j = 0; j < 32; j += 8)
        t[y + j][x] = W[(size_t)(by + y + j) * 1024 + src0 + x];
    __syncthreads();
#pragma unroll
    for (int j = 0; j < 32; j += 8)
        d_wtc[perm_hb(bx + y + j, by + x)] = __float2half_rn(t[x][y + j]);
}

__global__ void transpose_w(const float* __restrict__ W, __half* __restrict__ Wt, int Nc)
{
    __shared__ float t[32][33];
    int bx = blockIdx.x * 32;
    int by = blockIdx.y * 32;
    int x = threadIdx.x, y = threadIdx.y;
#pragma unroll
    for (int j = 0; j < 32; j += 8)
        t[y + j][x] = W[(size_t)(by + y + j) * Nc + bx + x];
    __syncthreads();
#pragma unroll
    for (int j = 0; j < 32; j += 8)
        Wt[perm_hb(bx + y + j, by + x)] = __float2half_rn(t[x][y + j]);
}

// =====================================================================
// x -> fp16 A-fragment layout
// =====================================================================
__global__ void permute_x(const float* __restrict__ x)
{
    int idx = blockIdx.x * 256 + threadIdx.x;
    int r = idx >> 7;
    int k = (idx & 127) * 4;
    float4 v = ((const float4*)x)[idx];
    *(__half2*)&d_xr[perm_h(r, k)]     = __floats2half2_rn(v.x, v.y);
    *(__half2*)&d_xr[perm_h(r, k + 2)] = __floats2half2_rn(v.z, v.w);
}

// =====================================================================
// per-channel params
// =====================================================================
__global__ void prep_params(const float* __restrict__ scale_p,
                            const float* __restrict__ power_p)
{
    int c = threadIdx.x;
    d_scinv[c] = 1.f / log1pf(expf(scale_p[c]));
    d_pw[c] = 1.f + 4.f / (1.f + expf(-power_p[c]));
}

// =====================================================================
// km = mean over n of kf (bf16 read)
// =====================================================================
__global__ void km_kernel()
{
    int bh  = blockIdx.x;
    int seg = blockIdx.y;
    int f   = threadIdx.x;
    const __nv_bfloat16* src =
        &d_kf[((size_t)bh * Nn + seg * (Nn / 8)) * Fn + f];
    float s = 0.f;
    for (int i = 0; i < Nn / 8; i++)
        s += __bfloat162float(src[(size_t)i * Fn]);
    atomicAdd(&d_km[bh * Fn + f], s * (1.f / (float)Nn));
}

// =====================================================================
// kvm via mma (tf32 path, unchanged)
// =====================================================================
#define KV_SEG 784

__global__ __launch_bounds__(256)
void kvm_mma()
{
    __shared__ __align__(16) uint16_t kfs[2][32][136];
    __shared__ __align__(16) float    vss[2][32][72];
    int bh = blockIdx.x, seg = blockIdx.y;
    int b = bh >> 3, h = bh & 7;
    int tid = threadIdx.x, wid = tid >> 5, lane = tid & 31;
    int lr = lane >> 2, lc = lane & 3;
    int wd = (wid & 1) * 64;
    int we = (wid >> 1) * 16;

    float c[4][2][4];
#pragma unroll
    for (int mt = 0; mt < 4; mt++)
#pragma unroll
        for (int nt = 0; nt < 2; nt++)
#pragma unroll
            for (int j = 0; j < 4; j++) c[mt][nt][j] = 0.f;

    int nbase = seg * KV_SEG;
    const int voff = h * 128 + 64;
#pragma unroll
    for (int j = 0; j < 2; j++) {
        int idx = tid + j * 256;
        int r = idx >> 4, cs = idx & 15;
        cp_async16(smem_u32(&kfs[0][r][cs * 8]),
                   &d_kf[((size_t)bh * Nn + nbase + r) * 128 + cs * 8]);
        cp_async16(smem_u32(&vss[0][r][cs * 4]),
                   &d_qgkv[((size_t)(b * Nn) + nbase + r) * 1024 + voff + cs * 4]);
    }
    CP_COMMIT();

    const int NT = 25;    // 24 full 32-row tiles + 16-row tail
    for (int t = 0; t < NT; t++) {
        if (t + 1 < NT) {
            int nb = (t + 1) & 1;
            int n0 = nbase + (t + 1) * 32;
            int rows = (t + 1 == NT - 1) ? 16 : 32;
#pragma unroll
            for (int j = 0; j < 2; j++) {
                int idx = tid + j * 256;
                int r = idx >> 4, cs = idx & 15;
                if (r < rows) {
                    cp_async16(smem_u32(&kfs[nb][r][cs * 8]),
                               &d_kf[((size_t)bh * Nn + n0 + r) * 128 + cs * 8]);
                    cp_async16(smem_u32(&vss[nb][r][cs * 4]),
                               &d_qgkv[((size_t)(b * Nn) + n0 + r) * 1024 + voff + cs * 4]);
                } else {
                    *(float4*)((char*)&kfs[nb][r][cs * 8]) = make_float4(0.f, 0.f, 0.f, 0.f);
                    *(float4*)&vss[nb][r][cs * 4] = make_float4(0.f, 0.f, 0.f, 0.f);
                }
            }
            CP_COMMIT();
            CP_WAIT(1);
        } else {
            CP_WAIT(0);
        }
        __syncthreads();
        int buf = t & 1;
#pragma unroll
        for (int kk = 0; kk < 4; kk++) {
            int k0 = kk * 8;
            uint32_t a[4][4];
#pragma unroll
            for (int mt = 0; mt < 4; mt++) {
                int db = wd + mt * 16;
                a[mt][0] = bf_as_tf32(kfs[buf][k0 + lc][db + lr]);
                a[mt][1] = bf_as_tf32(kfs[buf][k0 + lc][db + lr + 8]);
                a[mt][2] = bf_as_tf32(kfs[buf][k0 + lc + 4][db + lr]);
                a[mt][3] = bf_as_tf32(kfs[buf][k0 + lc + 4][db + lr + 8]);
            }
#pragma unroll
            for (int nt = 0; nt < 2; nt++) {
                int eb = we + nt * 8;
                uint32_t b0 = __float_as_uint(vss[buf][k0 + lc][eb + lr]);
                uint32_t b1 = __float_as_uint(vss[buf][k0 + lc + 4][eb + lr]);
#pragma unroll
                for (int mt = 0; mt < 4; mt++)
                    mma_tf32_16_8_8(c[mt][nt], a[mt], b0, b1);
            }
        }
        __syncthreads();
    }

    const float inv_n = 1.f / (float)Nn;
    float* dst = &d_kvm[(size_t)bh * 8192];
#pragma unroll
    for (int mt = 0; mt < 4; mt++) {
        int d0 = wd + mt * 16 + lr;
#pragma unroll
        for (int nt = 0; nt < 2; nt++) {
            int e0 = we + nt * 8 + 2 * lc;
            atomicAdd(&dst[d0 * 64 + e0],           c[mt][nt][0] * inv_n);
            atomicAdd(&dst[d0 * 64 + e0 + 1],       c[mt][nt][1] * inv_n);
            atomicAdd(&dst[(d0 + 8) * 64 + e0],     c[mt][nt][2] * inv_n);
            atomicAdd(&dst[(d0 + 8) * 64 + e0 + 1], c[mt][nt][3] * inv_n);
        }
    }
}

// =====================================================================
// build KVM2
// =====================================================================
__global__ void build_kvm2()
{
    int bh = blockIdx.x;
    const float* kvm = &d_kvm[(size_t)bh * 8192];
    const float* km  = &d_km[bh * 128];
    float* out = &d_kvm2[(size_t)bh * 9216];
    for (int i = threadIdx.x; i < 128 * 72; i += 256) {
        int dd = i / 72, col = i - dd * 72;
        float v;
        if (col < 32)       v = kvm[dd * 64 + col];
        else if (col < 64)  v = kvm[(dd ^ 64) * 64 + col];
        else if (col == 64) v = km[dd];
        else if (col == 65) v = km[dd ^ 64];
        else                v = 0.f;
        out[i] = v;
    }
}

// =====================================================================
// attention via mma; stores d_t fp16 in A-fragment layout
// =====================================================================
#define ATT_SMEM (36864 + 17408)

__global__ __launch_bounds__(128)
void attn_mma()
{
    extern __shared__ char smx[];
    float*    Bsm = (float*)smx;
    uint16_t* Asm = (uint16_t*)(smx + 36864);
    int m0 = blockIdx.x * 64, bh = blockIdx.y;
    int b = bh >> 3, h = bh & 7;
    int tid = threadIdx.x, wid = tid >> 5, lane = tid & 31;
    int lr = lane >> 2, lc = lane & 3;
    int wm = wid * 16;

    {
        const char* bsrc = (const char*)&d_kvm2[(size_t)bh * 9216];
#pragma unroll
        for (int j = 0; j < 18; j++) {
            int idx = tid + j * 128;
            cp_async16(smem_u32((char*)Bsm + idx * 16), bsrc + idx * 16);
        }
#pragma unroll
        for (int j = 0; j < 8; j++) {
            int idx = tid + j * 128;
            int r = idx >> 4, cs = idx & 15;
            cp_async16(smem_u32(&Asm[r * 136 + cs * 8]),
                       &d_qf[((size_t)bh * Nn + m0 + r) * 128 + cs * 8]);
        }
        CP_COMMIT(); CP_WAIT(0);
    }
    __syncthreads();

    float c[9][4];
#pragma unroll
    for (int nt = 0; nt < 9; nt++)
#pragma unroll
        for (int j = 0; j < 4; j++) c[nt][j] = 0.f;

#pragma unroll
    for (int kt = 0; kt < 16; kt++) {
        int k0 = kt * 8;
        uint32_t a[4];
        a[0] = bf_as_tf32(Asm[(wm + lr) * 136 + k0 + lc]);
        a[1] = bf_as_tf32(Asm[(wm + lr + 8) * 136 + k0 + lc]);
        a[2] = bf_as_tf32(Asm[(wm + lr) * 136 + k0 + lc + 4]);
        a[3] = bf_as_tf32(Asm[(wm + lr + 8) * 136 + k0 + lc + 4]);
#pragma unroll
        for (int nt = 0; nt < 9; nt++) {
            uint32_t b0 = __float_as_uint(Bsm[(k0 + lc) * 72 + nt * 8 + lr]);
            uint32_t b1 = __float_as_uint(Bsm[(k0 + lc + 4) * 72 + nt * 8 + lr]);
            mma_tf32_16_8_8(c[nt], a, b0, b1);
        }
    }

    int src = lane & 28;
    float den1a = __shfl_sync(0xffffffffu, c[8][0], src);
    float den2a = __shfl_sync(0xffffffffu, c[8][1], src);
    float den1b = __shfl_sync(0xffffffffu, c[8][2], src);
    float den2b = __shfl_sync(0xffffffffu, c[8][3], src);
    float z1a = 1.f / (den1a + 1e-6f), z2a = 1.f / (den2a + 1e-6f);
    float z1b = 1.f / (den1b + 1e-6f), z2b = 1.f / (den2b + 1e-6f);

    int ra = b * Nn + m0 + wm + lr;
    int rb = ra + 8;
#pragma unroll
    for (int nt = 0; nt < 8; nt++) {
        int col = nt * 8 + 2 * lc;
        float za = (col < 32) ? z1a : z2a;
        float zb = (col < 32) ? z1b : z2b;
        int k = h * 64 + col;
        *(__half2*)&d_t[perm_h(ra, k)] =
            __floats2half2_rn(c[nt][0] * za, c[nt][1] * za);
        *(__half2*)&d_t[perm_h(rb, k)] =
            __floats2half2_rn(c[nt][2] * zb, c[nt][3] * zb);
    }
}

// =====================================================================
// depthwise conv + gate; g|v layout; d_t fp16 fragment RMW
// =====================================================================
__global__ __launch_bounds__(512)
void conv_gate_kernel(const float* __restrict__ dwc_w,
                      const float* __restrict__ dwc_b)
{
    __shared__ float ws[64 * 25];
    __shared__ float bs[64];
    int y = blockIdx.x;
    int b = blockIdx.y;
    int c = threadIdx.x;
    int d = c & 63;
    int h = c >> 6;
    for (int i = c; i < 64 * 25; i += 512) ws[i] = dwc_w[i];
    if (c < 64) bs[c] = dwc_b[c];
    __syncthreads();

    const float* vbase = &d_qgkv[(size_t)(b * Nn) * 1024 + h * 128 + 64 + d];
    const float* gbase = &d_qgkv[(size_t)(b * Nn) * 1024 + h * 128 + d];

    float win[5][5];
#pragma unroll
    for (int dy = 0; dy < 5; dy++) {
        int yy = y + dy - 2;
        bool yok = (unsigned)yy < HW;
#pragma unroll
        for (int j = 0; j < 5; j++) {
            int xx = j - 2;
            win[dy][j] = (yok && (unsigned)xx < HW)
                         ? vbase[(size_t)(yy * HW + xx) * 1024] : 0.f;
        }
    }

    for (int x = 0; x < HW; x++) {
        float acc = bs[d];
#pragma unroll
        for (int dy = 0; dy < 5; dy++)
#pragma unroll
            for (int j = 0; j < 5; j++)
                acc = fmaf(win[dy][j], ws[d * 25 + dy * 5 + j], acc);

        int i1 = b * Nn + y * HW + x;
        float g = gbase[(size_t)(y * HW + x) * 1024];
        size_t pi = perm_h(i1, c);
        float tv = __half2float(d_t[pi]);
        d_t[pi] = __float2half_rn((tv + acc) * g);

        int xx = x + 3;
        bool xok = xx < HW;
#pragma unroll
        for (int dy = 0; dy < 5; dy++) {
#pragma unroll
            for (int j = 0; j < 4; j++) win[dy][j] = win[dy][j + 1];
            int yy = y + dy - 2;
            win[dy][4] = (xok && (unsigned)yy < HW)
                         ? vbase[(size_t)(yy * HW + xx) * 1024] : 0.f;
        }
    }
}

// =====================================================================
// launch (launch #3 == big gemm for ncu capture)
// =====================================================================
extern "C" void kernel_launch(void* const* d_in, const int* in_sizes, int n_in,
                              void* d_out, int out_size)
{
    const float* x       = (const float*)d_in[0];
    const float* qg_w    = (const float*)d_in[1];
    const float* kv_w    = (const float*)d_in[2];
    const float* proj_w  = (const float*)d_in[3];
    const float* proj_b  = (const float*)d_in[4];
    const float* pos_enc = (const float*)d_in[5];
    const float* scale_p = (const float*)d_in[6];
    const float* power_p = (const float*)d_in[7];
    const float* dwc_w   = (const float*)d_in[8];
    const float* dwc_b   = (const float*)d_in[9];
    float* out = (float*)d_out;

    __half *p_t, *p_wtc, *p_wt3, *p_xr;
    float *p_km, *p_kvm;
    cudaGetSymbolAddress((void**)&p_t,    d_t);
    cudaGetSymbolAddress((void**)&p_wtc,  d_wtc);
    cudaGetSymbolAddress((void**)&p_wt3,  d_wt3);
    cudaGetSymbolAddress((void**)&p_xr,   d_xr);
    cudaGetSymbolAddress((void**)&p_km,   d_km);
    cudaGetSymbolAddress((void**)&p_kvm,  d_kvm);

    cudaFuncSetAttribute(gemm_mma, cudaFuncAttributeMaxDynamicSharedMemorySize,
                         GEMM_SMEM);
    cudaFuncSetAttribute(attn_mma, cudaFuncAttributeMaxDynamicSharedMemorySize,
                         ATT_SMEM);

    cudaMemsetAsync(p_km,  0, Bn * NH * Fn * sizeof(float));
    cudaMemsetAsync(p_kvm, 0, Bn * NH * Fn * 64 * sizeof(float));

    dim3 tb(32, 8);
    prep_params<<<1, 512>>>(scale_p, power_p);                       // 0
    permute_x<<<Mrows * 128 / 256, 256>>>(x);                        // 1
    transpose_qgkv<<<dim3(64, 16), tb>>>(qg_w, kv_w);                // 2
    gemm_mma<<<dim3(16, Mrows / 128), 128, GEMM_SMEM>>>(             // 3 (profiled)
        p_xr, p_wtc, nullptr, nullptr, 1024, 1, pos_enc);
    transpose_w<<<dim3(16, 16), tb>>>(proj_w, p_wt3, 512);           // 4
    km_kernel<<<dim3(Bn * NH, 8), Fn>>>();                           // 5
    kvm_mma<<<dim3(Bn * NH, 4), 256>>>();                            // 6
    build_kvm2<<<Bn * NH, 256>>>();                                  // 7
    attn_mma<<<dim3(Nn / 64, Bn * NH), 128, ATT_SMEM>>>();           // 8
    conv_gate_kernel<<<dim3(HW, Bn), 512>>>(dwc_w, dwc_b);           // 9
    gemm_mma<<<dim3(4, Mrows / 128), 128, GEMM_SMEM>>>(              // 10
        p_t, p_wt3, proj_b, out, 512, 0, nullptr);
}

// round 15
// speedup vs baseline: 1.6423x; 1.0227x over previous
#include <cuda_runtime.h>
#include <cuda_bf16.h>
#include <cuda_fp16.h>
#include <math.h>
#include <stdint.h>

// ---------------- problem constants ----------------
#define Bn   16
#define Nn   3136        // 56*56
#define Cn   512
#define NH   8
#define HD   64
#define Fn   128         // 2*HD
#define Mrows (Bn*Nn)    // 50176
#define HW   56

// ---------------- scratch (device globals; no allocs allowed) --------------
__device__ __align__(16) float d_qgkv[Mrows * 1024];        // [b,n, (g_h|v_h) x8 heads]
__device__ __align__(16) __half d_xr[Mrows * 512];          // x fp16, A-FRAGMENT layout
__device__ __align__(16) __half d_qf[Bn*NH*Nn*Fn];          // q_sim  [bh,n,128] fp16
__device__ __align__(16) __half d_kf[Bn*NH*Nn*Fn];          // kf     [bh,n,128] fp16
__device__ __align__(16) float d_km[Bn*NH*Fn];              // mean over n
__device__ __align__(16) float d_kvm[Bn*NH*Fn*64];          // [bh,d(128),e(64)]
__device__ __align__(16) __half d_kvm2[Bn*NH*72*128];       // TRANSPOSED [bh,col(72),d(128)] fp16
__device__ __align__(16) __half d_t [Mrows * Cn];           // (xo+vd)*g fp16, A-FRAGMENT
__device__ __align__(16) __half d_wtc[2048 * 512];          // interleaved weights fp16 B-FRAG
__device__ __align__(16) __half d_wt3[512 * 512];           // proj_w^T fp16 B-FRAG
__device__ __align__(16) float d_scinv[Cn];
__device__ __align__(16) float d_pw[Cn];

// =====================================================================
// helpers (baseline PTX only)
// =====================================================================
__device__ __forceinline__ uint32_t smem_u32(const void* p) {
    uint32_t a;
    asm("{ .reg .u64 t; cvta.to.shared.u64 t, %1; cvt.u32.u64 %0, t; }"
        : "=r"(a) : "l"(p));
    return a;
}

__device__ __forceinline__ void cp_async16(uint32_t saddr, const void* gaddr) {
    asm volatile("cp.async.ca.shared.global [%0], [%1], 16;"
                 :: "r"(saddr), "l"(gaddr) : "memory");
}
#define CP_COMMIT() asm volatile("cp.async.commit_group;" ::: "memory")
#define CP_WAIT(N)  asm volatile("cp.async.wait_group %0;" :: "n"(N) : "memory")

__device__ __forceinline__ void mma_f16(float* c, const uint32_t* a,
                                        uint32_t b0, uint32_t b1) {
    asm volatile(
        "mma.sync.aligned.m16n8k16.row.col.f32.f16.f16.f32 "
        "{%0,%1,%2,%3}, {%4,%5,%6,%7}, {%8,%9}, {%0,%1,%2,%3};"
        : "+f"(c[0]), "+f"(c[1]), "+f"(c[2]), "+f"(c[3])
        : "r"(a[0]), "r"(a[1]), "r"(a[2]), "r"(a[3]), "r"(b0), "r"(b1));
}

__device__ __forceinline__ void mma_tf32_16_8_8(float* c, const uint32_t* a,
                                                uint32_t b0, uint32_t b1) {
    asm volatile(
        "mma.sync.aligned.m16n8k8.row.col.f32.tf32.tf32.f32 "
        "{%0,%1,%2,%3}, {%4,%5,%6,%7}, {%8,%9}, {%0,%1,%2,%3};"
        : "+f"(c[0]), "+f"(c[1]), "+f"(c[2]), "+f"(c[3])
        : "r"(a[0]), "r"(a[1]), "r"(a[2]), "r"(a[3]), "r"(b0), "r"(b1));
}

__device__ __forceinline__ uint32_t hf_as_tf32(uint16_t h) {
    __half x = *reinterpret_cast<__half*>(&h);
    return __float_as_uint(__half2float(x));
}

// A-operand fp16 fragment layout
__device__ __forceinline__ size_t perm_h(int r, int k) {
    return (size_t)(r >> 7) * 65536
         + (size_t)((((k >> 4) * 8 + ((r >> 4) & 7)) << 8)
         + (((r & 7) * 4 + ((k >> 1) & 3)) << 3)
         + ((((r >> 3) & 1) + (((k >> 3) & 1) << 1)) << 1)
         + (k & 1));
}

// B-operand fp16 fragment layout
__device__ __forceinline__ size_t perm_hb(int n, int k) {
    return (size_t)(n >> 7) * 65536
         + (size_t)((((k >> 4) * 8 + ((n >> 4) & 7)) << 8)
         + (((n & 7) * 4 + ((k >> 1) & 3)) << 3)
         + ((((((n >> 3) & 1) << 1) + ((k >> 3) & 1))) << 1)
         + (k & 1));
}

// =====================================================================
// fp16 tensor-core GEMM (unchanged from R13)
// =====================================================================
#define GEMM_SMEM (3 * 16384)      // 49152 B

__global__ __launch_bounds__(128, 2)
void gemm_mma(const __half* __restrict__ A, const __half* __restrict__ Bt,
              const float* __restrict__ bias, float* __restrict__ Cm, int Nc,
              int mode, const float* __restrict__ pos_enc)
{
    extern __shared__ __half smh[];
    __half* stage[3] = { smh, smh + 8192, smh + 16384 };
    const int tid = threadIdx.x;
    const int bn_panel = blockIdx.x;
    const int bm_panel = blockIdx.y;
    const int wid = tid >> 5, lane = tid & 31;
    const int lr = lane >> 2, lc = lane & 3;
    const int wmg = (wid & 1) * 4;
    const int wnp = (wid >> 1) * 4;

    const __half* Ab = A  + (size_t)bm_panel * 65536;
    const __half* Bb = Bt + (size_t)bn_panel * 65536;

    float c[4][8][4];
#pragma unroll
    for (int mt = 0; mt < 4; mt++)
#pragma unroll
        for (int nt = 0; nt < 8; nt++)
#pragma unroll
            for (int j = 0; j < 4; j++) c[mt][nt][j] = 0.f;

    auto issue_stage = [&](int buf, int t) {
        uint32_t sa = smem_u32(stage[buf]);
        const __half* as = Ab + t * 4096;
        const __half* bs = Bb + t * 4096;
#pragma unroll
        for (int i = 0; i < 4; i++) {
            int ch = tid + i * 128;
            cp_async16(sa + ch * 16, as + ch * 8);
        }
#pragma unroll
        for (int i = 0; i < 4; i++) {
            int ch = tid + i * 128;
            cp_async16(sa + 8192 + ch * 16, bs + ch * 8);
        }
        CP_COMMIT();
    };

    issue_stage(0, 0);
    issue_stage(1, 1);

    for (int t = 0; t < 16; t++) {
        CP_WAIT(1);
        __syncthreads();
        if (t + 2 < 16) issue_stage((t + 2) % 3, t + 2);
        else            CP_COMMIT();

        const uint4* sa4 = (const uint4*)stage[t % 3];
        const uint4* sb4 = (const uint4*)(stage[t % 3] + 4096);
#pragma unroll
        for (int kk = 0; kk < 2; kk++) {
            uint4 av[4], bv[4];
#pragma unroll
            for (int mt = 0; mt < 4; mt++)
                av[mt] = sa4[(kk * 8 + wmg + mt) * 32 + lane];
#pragma unroll
            for (int j = 0; j < 4; j++)
                bv[j] = sb4[(kk * 8 + wnp + j) * 32 + lane];
#pragma unroll
            for (int mt = 0; mt < 4; mt++) {
                uint32_t a[4] = { av[mt].x, av[mt].y, av[mt].z, av[mt].w };
#pragma unroll
                for (int j = 0; j < 4; j++) {
                    mma_f16(c[mt][2 * j],     a, bv[j].x, bv[j].y);
                    mma_f16(c[mt][2 * j + 1], a, bv[j].z, bv[j].w);
                }
            }
        }
    }

    if (mode == 0) {
#pragma unroll
        for (int mt = 0; mt < 4; mt++) {
            int row = bm_panel * 128 + (wid & 1) * 64 + mt * 16 + lr;
#pragma unroll
            for (int nt = 0; nt < 8; nt++) {
                int col = bn_panel * 128 + (wid >> 1) * 64 + nt * 8 + lc * 2;
                float2 v0 = make_float2(c[mt][nt][0], c[mt][nt][1]);
                float2 v1 = make_float2(c[mt][nt][2], c[mt][nt][3]);
                float b0 = bias[col], b1 = bias[col + 1];
                v0.x += b0; v0.y += b1;
                v1.x += b0; v1.y += b1;
                *(float2*)&Cm[(size_t)row * Nc + col] = v0;
                *(float2*)&Cm[(size_t)(row + 8) * Nc + col] = v1;
            }
        }
    } else if (bn_panel < 8) {
        const int h = bn_panel;
        const bool isq = (wid >> 1) == 0;
        __half* dst = isq ? d_qf : d_kf;
#pragma unroll
        for (int mt = 0; mt < 4; mt++) {
#pragma unroll
            for (int rh = 0; rh < 2; rh++) {
                int row = bm_panel * 128 + (wid & 1) * 64 + mt * 16 + lr + rh * 8;
                int b = row / Nn;
                int n = row - b * Nn;
                size_t fbase = ((size_t)(b * NH + h) * Nn + n) << 7;
#pragma unroll
                for (int nt = 0; nt < 8; nt++) {
                    int d0 = nt * 8 + lc * 2;
                    int c0 = h * 64 + d0;
                    float v0 = c[mt][nt][rh * 2 + 0];
                    float v1 = c[mt][nt][rh * 2 + 1];
                    if (!isq) {
                        v0 += pos_enc[n * Cn + c0];
                        v1 += pos_enc[n * Cn + c0 + 1];
                    }
                    v0 *= d_scinv[c0];
                    v1 *= d_scinv[c0 + 1];
                    float a0 = exp2f(d_pw[c0]     * __log2f(fabsf(v0)));
                    float a1 = exp2f(d_pw[c0 + 1] * __log2f(fabsf(v1)));
                    float pp0 = (v0 > 0.f) ? a0 : 0.f;
                    float pn0 = (v0 < 0.f) ? a0 : 0.f;
                    float pp1 = (v1 > 0.f) ? a1 : 0.f;
                    float pn1 = (v1 < 0.f) ? a1 : 0.f;
                    *(__half2*)&dst[fbase + d0] = __floats2half2_rn(pp0, pp1);
                    *(__half2*)&dst[fbase + 64 + d0] = __floats2half2_rn(pn0, pn1);
                }
            }
        }
    } else {
        int colbase = (bn_panel - 8) * 128 + (wid >> 1) * 64;
#pragma unroll
        for (int mt = 0; mt < 4; mt++) {
            int row = bm_panel * 128 + (wid & 1) * 64 + mt * 16 + lr;
#pragma unroll
            for (int nt = 0; nt < 8; nt++) {
                int col = colbase + nt * 8 + lc * 2;
                *(float2*)&d_qgkv[(size_t)row * 1024 + col] =
                    make_float2(c[mt][nt][0], c[mt][nt][1]);
                *(float2*)&d_qgkv[(size_t)(row + 8) * 1024 + col] =
                    make_float2(c[mt][nt][2], c[mt][nt][3]);
            }
        }
    }
}

// =====================================================================
// weight transposes -> fp16 B-fragment layout
// =====================================================================
__global__ void transpose_qgkv(const float* __restrict__ qg_w,
                               const float* __restrict__ kv_w)
{
    __shared__ float t[32][33];
    int bx = blockIdx.x * 32;
    int by = blockIdx.y * 32;
    int x = threadIdx.x, y = threadIdx.y;
    int p = bx >> 7;
    int o = bx & 127;
    int h = p & 7;
    const float* W = (o < 64) ? qg_w : kv_w;
    int src0 = ((p < 8) ? 0 : 512) + h * 64 + (o & 63);
#pragma unroll
    for (int j = 0; j < 32; j += 8)
        t[y + j][x] = W[(size_t)(by + y + j) * 1024 + src0 + x];
    __syncthreads();
#pragma unroll
    for (int j = 0; j < 32; j += 8)
        d_wtc[perm_hb(bx + y + j, by + x)] = __float2half_rn(t[x][y + j]);
}

__global__ void transpose_w(const float* __restrict__ W, __half* __restrict__ Wt, int Nc)
{
    __shared__ float t[32][33];
    int bx = blockIdx.x * 32;
    int by = blockIdx.y * 32;
    int x = threadIdx.x, y = threadIdx.y;
#pragma unroll
    for (int j = 0; j < 32; j += 8)
        t[y + j][x] = W[(size_t)(by + y + j) * Nc + bx + x];
    __syncthreads();
#pragma unroll
    for (int j = 0; j < 32; j += 8)
        Wt[perm_hb(bx + y + j, by + x)] = __float2half_rn(t[x][y + j]);
}

// =====================================================================
// x -> fp16 A-fragment layout
// =====================================================================
__global__ void permute_x(const float* __restrict__ x)
{
    int idx = blockIdx.x * 256 + threadIdx.x;
    int r = idx >> 7;
    int k = (idx & 127) * 4;
    float4 v = ((const float4*)x)[idx];
    *(__half2*)&d_xr[perm_h(r, k)]     = __floats2half2_rn(v.x, v.y);
    *(__half2*)&d_xr[perm_h(r, k + 2)] = __floats2half2_rn(v.z, v.w);
}

// =====================================================================
// per-channel params
// =====================================================================
__global__ void prep_params(const float* __restrict__ scale_p,
                            const float* __restrict__ power_p)
{
    int c = threadIdx.x;
    d_scinv[c] = 1.f / log1pf(expf(scale_p[c]));
    d_pw[c] = 1.f + 4.f / (1.f + expf(-power_p[c]));
}

// =====================================================================
// km = mean over n of kf (fp16 read)
// =====================================================================
__global__ void km_kernel()
{
    int bh  = blockIdx.x;
    int seg = blockIdx.y;
    int f   = threadIdx.x;
    const __half* src =
        &d_kf[((size_t)bh * Nn + seg * (Nn / 8)) * Fn + f];
    float s = 0.f;
    for (int i = 0; i < Nn / 8; i++)
        s += __half2float(src[(size_t)i * Fn]);
    atomicAdd(&d_km[bh * Fn + f], s * (1.f / (float)Nn));
}

// =====================================================================
// kvm via mma (tf32 math; fp16 kf source, exact conversion)
// =====================================================================
#define KV_SEG 784

__global__ __launch_bounds__(256)
void kvm_mma()
{
    __shared__ __align__(16) uint16_t kfs[2][32][136];
    __shared__ __align__(16) float    vss[2][32][72];
    int bh = blockIdx.x, seg = blockIdx.y;
    int b = bh >> 3, h = bh & 7;
    int tid = threadIdx.x, wid = tid >> 5, lane = tid & 31;
    int lr = lane >> 2, lc = lane & 3;
    int wd = (wid & 1) * 64;
    int we = (wid >> 1) * 16;

    float c[4][2][4];
#pragma unroll
    for (int mt = 0; mt < 4; mt++)
#pragma unroll
        for (int nt = 0; nt < 2; nt++)
#pragma unroll
            for (int j = 0; j < 4; j++) c[mt][nt][j] = 0.f;

    int nbase = seg * KV_SEG;
    const int voff = h * 128 + 64;
#pragma unroll
    for (int j = 0; j < 2; j++) {
        int idx = tid + j * 256;
        int r = idx >> 4, cs = idx & 15;
        cp_async16(smem_u32(&kfs[0][r][cs * 8]),
                   &d_kf[((size_t)bh * Nn + nbase + r) * 128 + cs * 8]);
        cp_async16(smem_u32(&vss[0][r][cs * 4]),
                   &d_qgkv[((size_t)(b * Nn) + nbase + r) * 1024 + voff + cs * 4]);
    }
    CP_COMMIT();

    const int NT = 25;
    for (int t = 0; t < NT; t++) {
        if (t + 1 < NT) {
            int nb = (t + 1) & 1;
            int n0 = nbase + (t + 1) * 32;
            int rows = (t + 1 == NT - 1) ? 16 : 32;
#pragma unroll
            for (int j = 0; j < 2; j++) {
                int idx = tid + j * 256;
                int r = idx >> 4, cs = idx & 15;
                if (r < rows) {
                    cp_async16(smem_u32(&kfs[nb][r][cs * 8]),
                               &d_kf[((size_t)bh * Nn + n0 + r) * 128 + cs * 8]);
                    cp_async16(smem_u32(&vss[nb][r][cs * 4]),
                               &d_qgkv[((size_t)(b * Nn) + n0 + r) * 1024 + voff + cs * 4]);
                } else {
                    *(float4*)((char*)&kfs[nb][r][cs * 8]) = make_float4(0.f, 0.f, 0.f, 0.f);
                    *(float4*)&vss[nb][r][cs * 4] = make_float4(0.f, 0.f, 0.f, 0.f);
                }
            }
            CP_COMMIT();
            CP_WAIT(1);
        } else {
            CP_WAIT(0);
        }
        __syncthreads();
        int buf = t & 1;
#pragma unroll
        for (int kk = 0; kk < 4; kk++) {
            int k0 = kk * 8;
            uint32_t a[4][4];
#pragma unroll
            for (int mt = 0; mt < 4; mt++) {
                int db = wd + mt * 16;
                a[mt][0] = hf_as_tf32(kfs[buf][k0 + lc][db + lr]);
                a[mt][1] = hf_as_tf32(kfs[buf][k0 + lc][db + lr + 8]);
                a[mt][2] = hf_as_tf32(kfs[buf][k0 + lc + 4][db + lr]);
                a[mt][3] = hf_as_tf32(kfs[buf][k0 + lc + 4][db + lr + 8]);
            }
#pragma unroll
            for (int nt = 0; nt < 2; nt++) {
                int eb = we + nt * 8;
                uint32_t b0 = __float_as_uint(vss[buf][k0 + lc][eb + lr]);
                uint32_t b1 = __float_as_uint(vss[buf][k0 + lc + 4][eb + lr]);
#pragma unroll
                for (int mt = 0; mt < 4; mt++)
                    mma_tf32_16_8_8(c[mt][nt], a[mt], b0, b1);
            }
        }
        __syncthreads();
    }

    const float inv_n = 1.f / (float)Nn;
    float* dst = &d_kvm[(size_t)bh * 8192];
#pragma unroll
    for (int mt = 0; mt < 4; mt++) {
        int d0 = wd + mt * 16 + lr;
#pragma unroll
        for (int nt = 0; nt < 2; nt++) {
            int e0 = we + nt * 8 + 2 * lc;
            atomicAdd(&dst[d0 * 64 + e0],           c[mt][nt][0] * inv_n);
            atomicAdd(&dst[d0 * 64 + e0 + 1],       c[mt][nt][1] * inv_n);
            atomicAdd(&dst[(d0 + 8) * 64 + e0],     c[mt][nt][2] * inv_n);
            atomicAdd(&dst[(d0 + 8) * 64 + e0 + 1], c[mt][nt][3] * inv_n);
        }
    }
}

// =====================================================================
// build KVM2 (transposed fp16): out[col*128 + d]
// =====================================================================
__global__ void build_kvm2()
{
    int bh = blockIdx.x;
    const float* kvm = &d_kvm[(size_t)bh * 8192];
    const float* km  = &d_km[bh * 128];
    __half* out = &d_kvm2[(size_t)bh * 9216];
    for (int i = threadIdx.x; i < 72 * 128; i += 256) {
        int col = i >> 7, dd = i & 127;
        float v;
        if (col < 32)       v = kvm[dd * 64 + col];
        else if (col < 64)  v = kvm[(dd ^ 64) * 64 + col];
        else if (col == 64) v = km[dd];
        else if (col == 65) v = km[dd ^ 64];
        else                v = 0.f;
        out[i] = __float2half_rn(v);
    }
}

// =====================================================================
// attention via fp16 mma (m16n8k16); stores d_t fp16 A-fragment layout
// =====================================================================
#define ATT_SMEM (17408 + 19584)   // Asm half[64][136] + BsmT half[72][136]

__global__ __launch_bounds__(128)
void attn_mma()
{
    extern __shared__ char smx[];
    uint16_t* Asm  = (uint16_t*)smx;            // [64][136]
    uint16_t* BsmT = (uint16_t*)(smx + 17408);  // [72][136]
    int m0 = blockIdx.x * 64, bh = blockIdx.y;
    int b = bh >> 3, h = bh & 7;
    int tid = threadIdx.x, wid = tid >> 5, lane = tid & 31;
    int lr = lane >> 2, lc = lane & 3;
    int wm = wid * 16;

    {
        const __half* bsrc = &d_kvm2[(size_t)bh * 9216];
#pragma unroll
        for (int j = 0; j < 9; j++) {         // 72*128/8 = 1152 chunks
            int ch = tid + j * 128;
            int r = ch >> 4, cs = ch & 15;
            cp_async16(smem_u32(&BsmT[r * 136 + cs * 8]), bsrc + r * 128 + cs * 8);
        }
#pragma unroll
        for (int j = 0; j < 8; j++) {
            int idx = tid + j * 128;
            int r = idx >> 4, cs = idx & 15;
            cp_async16(smem_u32(&Asm[r * 136 + cs * 8]),
                       &d_qf[((size_t)bh * Nn + m0 + r) * 128 + cs * 8]);
        }
        CP_COMMIT(); CP_WAIT(0);
    }
    __syncthreads();

    float c[9][4];
#pragma unroll
    for (int nt = 0; nt < 9; nt++)
#pragma unroll
        for (int j = 0; j < 4; j++) c[nt][j] = 0.f;

#pragma unroll
    for (int kt = 0; kt < 8; kt++) {
        int k0 = kt * 16;
        uint32_t a[4];
        a[0] = *(const uint32_t*)&Asm[(wm + lr) * 136 + k0 + 2 * lc];
        a[1] = *(const uint32_t*)&Asm[(wm + lr + 8) * 136 + k0 + 2 * lc];
        a[2] = *(const uint32_t*)&Asm[(wm + lr) * 136 + k0 + 8 + 2 * lc];
        a[3] = *(const uint32_t*)&Asm[(wm + lr + 8) * 136 + k0 + 8 + 2 * lc];
#pragma unroll
        for (int nt = 0; nt < 9; nt++) {
            uint32_t b0 = *(const uint32_t*)&BsmT[(nt * 8 + lr) * 136 + k0 + 2 * lc];
            uint32_t b1 = *(const uint32_t*)&BsmT[(nt * 8 + lr) * 136 + k0 + 8 + 2 * lc];
            mma_f16(c[nt], a, b0, b1);
        }
    }

    int src = lane & 28;
    float den1a = __shfl_sync(0xffffffffu, c[8][0], src);
    float den2a = __shfl_sync(0xffffffffu, c[8][1], src);
    float den1b = __shfl_sync(0xffffffffu, c[8][2], src);
    float den2b = __shfl_sync(0xffffffffu, c[8][3], src);
    float z1a = 1.f / (den1a + 1e-6f), z2a = 1.f / (den2a + 1e-6f);
    float z1b = 1.f / (den1b + 1e-6f), z2b = 1.f / (den2b + 1e-6f);

    int ra = b * Nn + m0 + wm + lr;
    int rb = ra + 8;
#pragma unroll
    for (int nt = 0; nt < 8; nt++) {
        int col = nt * 8 + 2 * lc;
        float za = (col < 32) ? z1a : z2a;
        float zb = (col < 32) ? z1b : z2b;
        int k = h * 64 + col;
        *(__half2*)&d_t[perm_h(ra, k)] =
            __floats2half2_rn(c[nt][0] * za, c[nt][1] * za);
        *(__half2*)&d_t[perm_h(rb, k)] =
            __floats2half2_rn(c[nt][2] * zb, c[nt][3] * zb);
    }
}

// =====================================================================
// depthwise conv + gate; g|v layout; d_t fp16 fragment RMW
// =====================================================================
__global__ __launch_bounds__(512)
void conv_gate_kernel(const float* __restrict__ dwc_w,
                      const float* __restrict__ dwc_b)
{
    __shared__ float ws[64 * 25];
    __shared__ float bs[64];
    int y = blockIdx.x;
    int b = blockIdx.y;
    int c = threadIdx.x;
    int d = c & 63;
    int h = c >> 6;
    for (int i = c; i < 64 * 25; i += 512) ws[i] = dwc_w[i];
    if (c < 64) bs[c] = dwc_b[c];
    __syncthreads();

    const float* vbase = &d_qgkv[(size_t)(b * Nn) * 1024 + h * 128 + 64 + d];
    const float* gbase = &d_qgkv[(size_t)(b * Nn) * 1024 + h * 128 + d];

    float win[5][5];
#pragma unroll
    for (int dy = 0; dy < 5; dy++) {
        int yy = y + dy - 2;
        bool yok = (unsigned)yy < HW;
#pragma unroll
        for (int j = 0; j < 5; j++) {
            int xx = j - 2;
            win[dy][j] = (yok && (unsigned)xx < HW)
                         ? vbase[(size_t)(yy * HW + xx) * 1024] : 0.f;
        }
    }

    for (int x = 0; x < HW; x++) {
        float acc = bs[d];
#pragma unroll
        for (int dy = 0; dy < 5; dy++)
#pragma unroll
            for (int j = 0; j < 5; j++)
                acc = fmaf(win[dy][j], ws[d * 25 + dy * 5 + j], acc);

        int i1 = b * Nn + y * HW + x;
        float g = gbase[(size_t)(y * HW + x) * 1024];
        size_t pi = perm_h(i1, c);
        float tv = __half2float(d_t[pi]);
        d_t[pi] = __float2half_rn((tv + acc) * g);

        int xx = x + 3;
        bool xok = xx < HW;
#pragma unroll
        for (int dy = 0; dy < 5; dy++) {
#pragma unroll
            for (int j = 0; j < 4; j++) win[dy][j] = win[dy][j + 1];
            int yy = y + dy - 2;
            win[dy][4] = (xok && (unsigned)yy < HW)
                         ? vbase[(size_t)(yy * HW + xx) * 1024] : 0.f;
        }
    }
}

// =====================================================================
// launch (launch #3 == big gemm for ncu capture)
// =====================================================================
extern "C" void kernel_launch(void* const* d_in, const int* in_sizes, int n_in,
                              void* d_out, int out_size)
{
    const float* x       = (const float*)d_in[0];
    const float* qg_w    = (const float*)d_in[1];
    const float* kv_w    = (const float*)d_in[2];
    const float* proj_w  = (const float*)d_in[3];
    const float* proj_b  = (const float*)d_in[4];
    const float* pos_enc = (const float*)d_in[5];
    const float* scale_p = (const float*)d_in[6];
    const float* power_p = (const float*)d_in[7];
    const float* dwc_w   = (const float*)d_in[8];
    const float* dwc_b   = (const float*)d_in[9];
    float* out = (float*)d_out;

    __half *p_t, *p_wtc, *p_wt3, *p_xr;
    float *p_km, *p_kvm;
    cudaGetSymbolAddress((void**)&p_t,    d_t);
    cudaGetSymbolAddress((void**)&p_wtc,  d_wtc);
    cudaGetSymbolAddress((void**)&p_wt3,  d_wt3);
    cudaGetSymbolAddress((void**)&p_xr,   d_xr);
    cudaGetSymbolAddress((void**)&p_km,   d_km);
    cudaGetSymbolAddress((void**)&p_kvm,  d_kvm);

    cudaFuncSetAttribute(gemm_mma, cudaFuncAttributeMaxDynamicSharedMemorySize,
                         GEMM_SMEM);
    cudaFuncSetAttribute(attn_mma, cudaFuncAttributeMaxDynamicSharedMemorySize,
                         ATT_SMEM);

    cudaMemsetAsync(p_km,  0, Bn * NH * Fn * sizeof(float));
    cudaMemsetAsync(p_kvm, 0, Bn * NH * Fn * 64 * sizeof(float));

    dim3 tb(32, 8);
    prep_params<<<1, 512>>>(scale_p, power_p);                       // 0
    permute_x<<<Mrows * 128 / 256, 256>>>(x);                        // 1
    transpose_qgkv<<<dim3(64, 16), tb>>>(qg_w, kv_w);                // 2
    gemm_mma<<<dim3(16, Mrows / 128), 128, GEMM_SMEM>>>(             // 3 (profiled)
        p_xr, p_wtc, nullptr, nullptr, 1024, 1, pos_enc);
    transpose_w<<<dim3(16, 16), tb>>>(proj_w, p_wt3, 512);           // 4
    km_kernel<<<dim3(Bn * NH, 8), Fn>>>();                           // 5
    kvm_mma<<<dim3(Bn * NH, 4), 256>>>();                            // 6
    build_kvm2<<<Bn * NH, 256>>>();                                  // 7
    attn_mma<<<dim3(Nn / 64, Bn * NH), 128, ATT_SMEM>>>();           // 8
    conv_gate_kernel<<<dim3(HW, Bn), 512>>>(dwc_w, dwc_b);           // 9
    gemm_mma<<<dim3(4, Mrows / 128), 128, GEMM_SMEM>>>(              // 10
        p_t, p_wt3, proj_b, out, 512, 0, nullptr);
}

// round 16
// speedup vs baseline: 1.7352x; 1.0565x over previous
#include <cuda_runtime.h>
#include <cuda_bf16.h>
#include <cuda_fp16.h>
#include <math.h>
#include <stdint.h>

// ---------------- problem constants ----------------
#define Bn   16
#define Nn   3136        // 56*56
#define Cn   512
#define NH   8
#define HD   64
#define Fn   128         // 2*HD
#define Mrows (Bn*Nn)    // 50176
#define HW   56

// ---------------- scratch (device globals; no allocs allowed) --------------
__device__ __align__(16) float d_qgkv[Mrows * 1024];        // [b,n, (g_h|v_h) x8 heads]
__device__ __align__(16) __half d_xr[Mrows * 512];          // x fp16, A-FRAGMENT layout
__device__ __align__(16) __half d_qf[Bn*NH*Nn*Fn];          // q_sim  [bh,n,128] fp16
__device__ __align__(16) __half d_kf[Bn*NH*Nn*Fn];          // kf     [bh,n,128] fp16
__device__ __align__(16) float d_km[Bn*NH*Fn];              // mean over n
__device__ __align__(16) float d_kvm[Bn*NH*Fn*64];          // [bh,d(128),e(64)]
__device__ __align__(16) __half d_kvm2[Bn*NH*72*128];       // TRANSPOSED [bh,col(72),d(128)] fp16
__device__ __align__(16) __half d_t [Mrows * Cn];           // (xo+vd)*g fp16, A-FRAGMENT
__device__ __align__(16) __half d_wtc[2048 * 512];          // interleaved weights fp16 B-FRAG
__device__ __align__(16) __half d_wt3[512 * 512];           // proj_w^T fp16 B-FRAG
__device__ __align__(16) float d_scinv[Cn];
__device__ __align__(16) float d_pw[Cn];

// =====================================================================
// helpers (baseline PTX only)
// =====================================================================
__device__ __forceinline__ uint32_t smem_u32(const void* p) {
    uint32_t a;
    asm("{ .reg .u64 t; cvta.to.shared.u64 t, %1; cvt.u32.u64 %0, t; }"
        : "=r"(a) : "l"(p));
    return a;
}

__device__ __forceinline__ void cp_async16(uint32_t saddr, const void* gaddr) {
    asm volatile("cp.async.ca.shared.global [%0], [%1], 16;"
                 :: "r"(saddr), "l"(gaddr) : "memory");
}
#define CP_COMMIT() asm volatile("cp.async.commit_group;" ::: "memory")
#define CP_WAIT(N)  asm volatile("cp.async.wait_group %0;" :: "n"(N) : "memory")

__device__ __forceinline__ void mma_f16(float* c, const uint32_t* a,
                                        uint32_t b0, uint32_t b1) {
    asm volatile(
        "mma.sync.aligned.m16n8k16.row.col.f32.f16.f16.f32 "
        "{%0,%1,%2,%3}, {%4,%5,%6,%7}, {%8,%9}, {%0,%1,%2,%3};"
        : "+f"(c[0]), "+f"(c[1]), "+f"(c[2]), "+f"(c[3])
        : "r"(a[0]), "r"(a[1]), "r"(a[2]), "r"(a[3]), "r"(b0), "r"(b1));
}

__device__ __forceinline__ void mma_tf32_16_8_8(float* c, const uint32_t* a,
                                                uint32_t b0, uint32_t b1) {
    asm volatile(
        "mma.sync.aligned.m16n8k8.row.col.f32.tf32.tf32.f32 "
        "{%0,%1,%2,%3}, {%4,%5,%6,%7}, {%8,%9}, {%0,%1,%2,%3};"
        : "+f"(c[0]), "+f"(c[1]), "+f"(c[2]), "+f"(c[3])
        : "r"(a[0]), "r"(a[1]), "r"(a[2]), "r"(a[3]), "r"(b0), "r"(b1));
}

__device__ __forceinline__ uint32_t hf_as_tf32(uint16_t h) {
    __half x = *reinterpret_cast<__half*>(&h);
    return __float_as_uint(__half2float(x));
}

// A-operand fp16 fragment layout
__device__ __forceinline__ size_t perm_h(int r, int k) {
    return (size_t)(r >> 7) * 65536
         + (size_t)((((k >> 4) * 8 + ((r >> 4) & 7)) << 8)
         + (((r & 7) * 4 + ((k >> 1) & 3)) << 3)
         + ((((r >> 3) & 1) + (((k >> 3) & 1) << 1)) << 1)
         + (k & 1));
}

// B-operand fp16 fragment layout
__device__ __forceinline__ size_t perm_hb(int n, int k) {
    return (size_t)(n >> 7) * 65536
         + (size_t)((((k >> 4) * 8 + ((n >> 4) & 7)) << 8)
         + (((n & 7) * 4 + ((k >> 1) & 3)) << 3)
         + ((((((n >> 3) & 1) << 1) + ((k >> 3) & 1))) << 1)
         + (k & 1));
}

// =====================================================================
// fp16 tensor-core GEMM. A staged via cp.async smem (3 x 8KB);
// B read DIRECTLY from L2 as LDG.128 fragments (weights are L2-resident),
// prefetched one k-tile ahead in registers.
// CTA 128x128, 4 warps (2m x 2n), warp 64x64, 2 CTAs/SM.
// =====================================================================
#define GEMM_SMEM (3 * 8192)       // 24576 B (A only)

__global__ __launch_bounds__(128, 2)
void gemm_mma(const __half* __restrict__ A, const __half* __restrict__ Bt,
              const float* __restrict__ bias, float* __restrict__ Cm, int Nc,
              int mode, const float* __restrict__ pos_enc)
{
    extern __shared__ __half smh[];
    __half* stage[3] = { smh, smh + 4096, smh + 8192 };
    const int tid = threadIdx.x;
    const int bn_panel = blockIdx.x;
    const int bm_panel = blockIdx.y;
    const int wid = tid >> 5, lane = tid & 31;
    const int lr = lane >> 2, lc = lane & 3;
    const int wmg = (wid & 1) * 4;
    const int wnp = (wid >> 1) * 4;

    const __half* Ab = A + (size_t)bm_panel * 65536;
    const uint4* Bg = (const uint4*)(Bt + (size_t)bn_panel * 65536);

    float c[4][8][4];
#pragma unroll
    for (int mt = 0; mt < 4; mt++)
#pragma unroll
        for (int nt = 0; nt < 8; nt++)
#pragma unroll
            for (int j = 0; j < 4; j++) c[mt][nt][j] = 0.f;

    auto issue_stage = [&](int buf, int t) {
        uint32_t sa = smem_u32(stage[buf]);
        const __half* as = Ab + t * 4096;
#pragma unroll
        for (int i = 0; i < 4; i++) {
            int ch = tid + i * 128;
            cp_async16(sa + ch * 16, as + ch * 8);
        }
        CP_COMMIT();
    };

    // B fragments for tile 0 (register prefetch)
    uint4 bv[2][4];
#pragma unroll
    for (int kk = 0; kk < 2; kk++)
#pragma unroll
        for (int j = 0; j < 4; j++)
            bv[kk][j] = Bg[(kk * 8 + wnp + j) * 32 + lane];

    issue_stage(0, 0);
    issue_stage(1, 1);

    for (int t = 0; t < 16; t++) {
        CP_WAIT(1);
        __syncthreads();
        if (t + 2 < 16) issue_stage((t + 2) % 3, t + 2);
        else            CP_COMMIT();

        const uint4* sa4 = (const uint4*)stage[t % 3];
#pragma unroll
        for (int kk = 0; kk < 2; kk++) {
            uint4 av[4];
#pragma unroll
            for (int mt = 0; mt < 4; mt++)
                av[mt] = sa4[(kk * 8 + wmg + mt) * 32 + lane];
#pragma unroll
            for (int mt = 0; mt < 4; mt++) {
                uint32_t a[4] = { av[mt].x, av[mt].y, av[mt].z, av[mt].w };
#pragma unroll
                for (int j = 0; j < 4; j++) {
                    mma_f16(c[mt][2 * j],     a, bv[kk][j].x, bv[kk][j].y);
                    mma_f16(c[mt][2 * j + 1], a, bv[kk][j].z, bv[kk][j].w);
                }
            }
        }
        if (t + 1 < 16) {      // prefetch B fragments for next tile (L2 hit)
            const uint4* Bn_ = Bg + (t + 1) * 512;
#pragma unroll
            for (int kk = 0; kk < 2; kk++)
#pragma unroll
                for (int j = 0; j < 4; j++)
                    bv[kk][j] = Bn_[(kk * 8 + wnp + j) * 32 + lane];
        }
    }

    if (mode == 0) {
#pragma unroll
        for (int mt = 0; mt < 4; mt++) {
            int row = bm_panel * 128 + (wid & 1) * 64 + mt * 16 + lr;
#pragma unroll
            for (int nt = 0; nt < 8; nt++) {
                int col = bn_panel * 128 + (wid >> 1) * 64 + nt * 8 + lc * 2;
                float2 v0 = make_float2(c[mt][nt][0], c[mt][nt][1]);
                float2 v1 = make_float2(c[mt][nt][2], c[mt][nt][3]);
                float b0 = bias[col], b1 = bias[col + 1];
                v0.x += b0; v0.y += b1;
                v1.x += b0; v1.y += b1;
                *(float2*)&Cm[(size_t)row * Nc + col] = v0;
                *(float2*)&Cm[(size_t)(row + 8) * Nc + col] = v1;
            }
        }
    } else if (bn_panel < 8) {
        const int h = bn_panel;
        const bool isq = (wid >> 1) == 0;
        __half* dst = isq ? d_qf : d_kf;
#pragma unroll
        for (int mt = 0; mt < 4; mt++) {
#pragma unroll
            for (int rh = 0; rh < 2; rh++) {
                int row = bm_panel * 128 + (wid & 1) * 64 + mt * 16 + lr + rh * 8;
                int b = row / Nn;
                int n = row - b * Nn;
                size_t fbase = ((size_t)(b * NH + h) * Nn + n) << 7;
#pragma unroll
                for (int nt = 0; nt < 8; nt++) {
                    int d0 = nt * 8 + lc * 2;
                    int c0 = h * 64 + d0;
                    float v0 = c[mt][nt][rh * 2 + 0];
                    float v1 = c[mt][nt][rh * 2 + 1];
                    if (!isq) {
                        v0 += pos_enc[n * Cn + c0];
                        v1 += pos_enc[n * Cn + c0 + 1];
                    }
                    v0 *= d_scinv[c0];
                    v1 *= d_scinv[c0 + 1];
                    float a0 = exp2f(d_pw[c0]     * __log2f(fabsf(v0)));
                    float a1 = exp2f(d_pw[c0 + 1] * __log2f(fabsf(v1)));
                    float pp0 = (v0 > 0.f) ? a0 : 0.f;
                    float pn0 = (v0 < 0.f) ? a0 : 0.f;
                    float pp1 = (v1 > 0.f) ? a1 : 0.f;
                    float pn1 = (v1 < 0.f) ? a1 : 0.f;
                    *(__half2*)&dst[fbase + d0] = __floats2half2_rn(pp0, pp1);
                    *(__half2*)&dst[fbase + 64 + d0] = __floats2half2_rn(pn0, pn1);
                }
            }
        }
    } else {
        int colbase = (bn_panel - 8) * 128 + (wid >> 1) * 64;
#pragma unroll
        for (int mt = 0; mt < 4; mt++) {
            int row = bm_panel * 128 + (wid & 1) * 64 + mt * 16 + lr;
#pragma unroll
            for (int nt = 0; nt < 8; nt++) {
                int col = colbase + nt * 8 + lc * 2;
                *(float2*)&d_qgkv[(size_t)row * 1024 + col] =
                    make_float2(c[mt][nt][0], c[mt][nt][1]);
                *(float2*)&d_qgkv[(size_t)(row + 8) * 1024 + col] =
                    make_float2(c[mt][nt][2], c[mt][nt][3]);
            }
        }
    }
}

// =====================================================================
// weight transposes -> fp16 B-fragment layout
// =====================================================================
__global__ void transpose_qgkv(const float* __restrict__ qg_w,
                               const float* __restrict__ kv_w)
{
    __shared__ float t[32][33];
    int bx = blockIdx.x * 32;
    int by = blockIdx.y * 32;
    int x = threadIdx.x, y = threadIdx.y;
    int p = bx >> 7;
    int o = bx & 127;
    int h = p & 7;
    const float* W = (o < 64) ? qg_w : kv_w;
    int src0 = ((p < 8) ? 0 : 512) + h * 64 + (o & 63);
#pragma unroll
    for (int j = 0; j < 32; j += 8)
        t[y + j][x] = W[(size_t)(by + y + j) * 1024 + src0 + x];
    __syncthreads();
#pragma unroll
    for (int j = 0; j < 32; j += 8)
        d_wtc[perm_hb(bx + y + j, by + x)] = __float2half_rn(t[x][y + j]);
}

__global__ void transpose_w(const float* __restrict__ W, __half* __restrict__ Wt, int Nc)
{
    __shared__ float t[32][33];
    int bx = blockIdx.x * 32;
    int by = blockIdx.y * 32;
    int x = threadIdx.x, y = threadIdx.y;
#pragma unroll
    for (int j = 0; j < 32; j += 8)
        t[y + j][x] = W[(size_t)(by + y + j) * Nc + bx + x];
    __syncthreads();
#pragma unroll
    for (int j = 0; j < 32; j += 8)
        Wt[perm_hb(bx + y + j, by + x)] = __float2half_rn(t[x][y + j]);
}

// =====================================================================
// x -> fp16 A-fragment layout
// =====================================================================
__global__ void permute_x(const float* __restrict__ x)
{
    int idx = blockIdx.x * 256 + threadIdx.x;
    int r = idx >> 7;
    int k = (idx & 127) * 4;
    float4 v = ((const float4*)x)[idx];
    *(__half2*)&d_xr[perm_h(r, k)]     = __floats2half2_rn(v.x, v.y);
    *(__half2*)&d_xr[perm_h(r, k + 2)] = __floats2half2_rn(v.z, v.w);
}

// =====================================================================
// per-channel params
// =====================================================================
__global__ void prep_params(const float* __restrict__ scale_p,
                            const float* __restrict__ power_p)
{
    int c = threadIdx.x;
    d_scinv[c] = 1.f / log1pf(expf(scale_p[c]));
    d_pw[c] = 1.f + 4.f / (1.f + expf(-power_p[c]));
}

// =====================================================================
// km = mean over n of kf (fp16 read)
// =====================================================================
__global__ void km_kernel()
{
    int bh  = blockIdx.x;
    int seg = blockIdx.y;
    int f   = threadIdx.x;
    const __half* src =
        &d_kf[((size_t)bh * Nn + seg * (Nn / 8)) * Fn + f];
    float s = 0.f;
    for (int i = 0; i < Nn / 8; i++)
        s += __half2float(src[(size_t)i * Fn]);
    atomicAdd(&d_km[bh * Fn + f], s * (1.f / (float)Nn));
}

// =====================================================================
// kvm via mma (tf32 math; fp16 kf source, exact conversion)
// =====================================================================
#define KV_SEG 784

__global__ __launch_bounds__(256)
void kvm_mma()
{
    __shared__ __align__(16) uint16_t kfs[2][32][136];
    __shared__ __align__(16) float    vss[2][32][72];
    int bh = blockIdx.x, seg = blockIdx.y;
    int b = bh >> 3, h = bh & 7;
    int tid = threadIdx.x, wid = tid >> 5, lane = tid & 31;
    int lr = lane >> 2, lc = lane & 3;
    int wd = (wid & 1) * 64;
    int we = (wid >> 1) * 16;

    float c[4][2][4];
#pragma unroll
    for (int mt = 0; mt < 4; mt++)
#pragma unroll
        for (int nt = 0; nt < 2; nt++)
#pragma unroll
            for (int j = 0; j < 4; j++) c[mt][nt][j] = 0.f;

    int nbase = seg * KV_SEG;
    const int voff = h * 128 + 64;
#pragma unroll
    for (int j = 0; j < 2; j++) {
        int idx = tid + j * 256;
        int r = idx >> 4, cs = idx & 15;
        cp_async16(smem_u32(&kfs[0][r][cs * 8]),
                   &d_kf[((size_t)bh * Nn + nbase + r) * 128 + cs * 8]);
        cp_async16(smem_u32(&vss[0][r][cs * 4]),
                   &d_qgkv[((size_t)(b * Nn) + nbase + r) * 1024 + voff + cs * 4]);
    }
    CP_COMMIT();

    const int NT = 25;
    for (int t = 0; t < NT; t++) {
        if (t + 1 < NT) {
            int nb = (t + 1) & 1;
            int n0 = nbase + (t + 1) * 32;
            int rows = (t + 1 == NT - 1) ? 16 : 32;
#pragma unroll
            for (int j = 0; j < 2; j++) {
                int idx = tid + j * 256;
                int r = idx >> 4, cs = idx & 15;
                if (r < rows) {
                    cp_async16(smem_u32(&kfs[nb][r][cs * 8]),
                               &d_kf[((size_t)bh * Nn + n0 + r) * 128 + cs * 8]);
                    cp_async16(smem_u32(&vss[nb][r][cs * 4]),
                               &d_qgkv[((size_t)(b * Nn) + n0 + r) * 1024 + voff + cs * 4]);
                } else {
                    *(float4*)((char*)&kfs[nb][r][cs * 8]) = make_float4(0.f, 0.f, 0.f, 0.f);
                    *(float4*)&vss[nb][r][cs * 4] = make_float4(0.f, 0.f, 0.f, 0.f);
                }
            }
            CP_COMMIT();
            CP_WAIT(1);
        } else {
            CP_WAIT(0);
        }
        __syncthreads();
        int buf = t & 1;
#pragma unroll
        for (int kk = 0; kk < 4; kk++) {
            int k0 = kk * 8;
            uint32_t a[4][4];
#pragma unroll
            for (int mt = 0; mt < 4; mt++) {
                int db = wd + mt * 16;
                a[mt][0] = hf_as_tf32(kfs[buf][k0 + lc][db + lr]);
                a[mt][1] = hf_as_tf32(kfs[buf][k0 + lc][db + lr + 8]);
                a[mt][2] = hf_as_tf32(kfs[buf][k0 + lc + 4][db + lr]);
                a[mt][3] = hf_as_tf32(kfs[buf][k0 + lc + 4][db + lr + 8]);
            }
#pragma unroll
            for (int nt = 0; nt < 2; nt++) {
                int eb = we + nt * 8;
                uint32_t b0 = __float_as_uint(vss[buf][k0 + lc][eb + lr]);
                uint32_t b1 = __float_as_uint(vss[buf][k0 + lc + 4][eb + lr]);
#pragma unroll
                for (int mt = 0; mt < 4; mt++)
                    mma_tf32_16_8_8(c[mt][nt], a[mt], b0, b1);
            }
        }
        __syncthreads();
    }

    const float inv_n = 1.f / (float)Nn;
    float* dst = &d_kvm[(size_t)bh * 8192];
#pragma unroll
    for (int mt = 0; mt < 4; mt++) {
        int d0 = wd + mt * 16 + lr;
#pragma unroll
        for (int nt = 0; nt < 2; nt++) {
            int e0 = we + nt * 8 + 2 * lc;
            atomicAdd(&dst[d0 * 64 + e0],           c[mt][nt][0] * inv_n);
            atomicAdd(&dst[d0 * 64 + e0 + 1],       c[mt][nt][1] * inv_n);
            atomicAdd(&dst[(d0 + 8) * 64 + e0],     c[mt][nt][2] * inv_n);
            atomicAdd(&dst[(d0 + 8) * 64 + e0 + 1], c[mt][nt][3] * inv_n);
        }
    }
}

// =====================================================================
// build KVM2 (transposed fp16): out[col*128 + d]
// =====================================================================
__global__ void build_kvm2()
{
    int bh = blockIdx.x;
    const float* kvm = &d_kvm[(size_t)bh * 8192];
    const float* km  = &d_km[bh * 128];
    __half* out = &d_kvm2[(size_t)bh * 9216];
    for (int i = threadIdx.x; i < 72 * 128; i += 256) {
        int col = i >> 7, dd = i & 127;
        float v;
        if (col < 32)       v = kvm[dd * 64 + col];
        else if (col < 64)  v = kvm[(dd ^ 64) * 64 + col];
        else if (col == 64) v = km[dd];
        else if (col == 65) v = km[dd ^ 64];
        else                v = 0.f;
        out[i] = __float2half_rn(v);
    }
}

// =====================================================================
// attention via fp16 mma (m16n8k16); stores d_t fp16 A-fragment layout
// =====================================================================
#define ATT_SMEM (17408 + 19584)   // Asm half[64][136] + BsmT half[72][136]

__global__ __launch_bounds__(128)
void attn_mma()
{
    extern __shared__ char smx[];
    uint16_t* Asm  = (uint16_t*)smx;            // [64][136]
    uint16_t* BsmT = (uint16_t*)(smx + 17408);  // [72][136]
    int m0 = blockIdx.x * 64, bh = blockIdx.y;
    int b = bh >> 3, h = bh & 7;
    int tid = threadIdx.x, wid = tid >> 5, lane = tid & 31;
    int lr = lane >> 2, lc = lane & 3;
    int wm = wid * 16;

    {
        const __half* bsrc = &d_kvm2[(size_t)bh * 9216];
#pragma unroll
        for (int j = 0; j < 9; j++) {
            int ch = tid + j * 128;
            int r = ch >> 4, cs = ch & 15;
            cp_async16(smem_u32(&BsmT[r * 136 + cs * 8]), bsrc + r * 128 + cs * 8);
        }
#pragma unroll
        for (int j = 0; j < 8; j++) {
            int idx = tid + j * 128;
            int r = idx >> 4, cs = idx & 15;
            cp_async16(smem_u32(&Asm[r * 136 + cs * 8]),
                       &d_qf[((size_t)bh * Nn + m0 + r) * 128 + cs * 8]);
        }
        CP_COMMIT(); CP_WAIT(0);
    }
    __syncthreads();

    float c[9][4];
#pragma unroll
    for (int nt = 0; nt < 9; nt++)
#pragma unroll
        for (int j = 0; j < 4; j++) c[nt][j] = 0.f;

#pragma unroll
    for (int kt = 0; kt < 8; kt++) {
        int k0 = kt * 16;
        uint32_t a[4];
        a[0] = *(const uint32_t*)&Asm[(wm + lr) * 136 + k0 + 2 * lc];
        a[1] = *(const uint32_t*)&Asm[(wm + lr + 8) * 136 + k0 + 2 * lc];
        a[2] = *(const uint32_t*)&Asm[(wm + lr) * 136 + k0 + 8 + 2 * lc];
        a[3] = *(const uint32_t*)&Asm[(wm + lr + 8) * 136 + k0 + 8 + 2 * lc];
#pragma unroll
        for (int nt = 0; nt < 9; nt++) {
            uint32_t b0 = *(const uint32_t*)&BsmT[(nt * 8 + lr) * 136 + k0 + 2 * lc];
            uint32_t b1 = *(const uint32_t*)&BsmT[(nt * 8 + lr) * 136 + k0 + 8 + 2 * lc];
            mma_f16(c[nt], a, b0, b1);
        }
    }

    int src = lane & 28;
    float den1a = __shfl_sync(0xffffffffu, c[8][0], src);
    float den2a = __shfl_sync(0xffffffffu, c[8][1], src);
    float den1b = __shfl_sync(0xffffffffu, c[8][2], src);
    float den2b = __shfl_sync(0xffffffffu, c[8][3], src);
    float z1a = 1.f / (den1a + 1e-6f), z2a = 1.f / (den2a + 1e-6f);
    float z1b = 1.f / (den1b + 1e-6f), z2b = 1.f / (den2b + 1e-6f);

    int ra = b * Nn + m0 + wm + lr;
    int rb = ra + 8;
#pragma unroll
    for (int nt = 0; nt < 8; nt++) {
        int col = nt * 8 + 2 * lc;
        float za = (col < 32) ? z1a : z2a;
        float zb = (col < 32) ? z1b : z2b;
        int k = h * 64 + col;
        *(__half2*)&d_t[perm_h(ra, k)] =
            __floats2half2_rn(c[nt][0] * za, c[nt][1] * za);
        *(__half2*)&d_t[perm_h(rb, k)] =
            __floats2half2_rn(c[nt][2] * zb, c[nt][3] * zb);
    }
}

// =====================================================================
// depthwise conv + gate; g|v layout; d_t fp16 fragment RMW
// =====================================================================
__global__ __launch_bounds__(512)
void conv_gate_kernel(const float* __restrict__ dwc_w,
                      const float* __restrict__ dwc_b)
{
    __shared__ float ws[64 * 25];
    __shared__ float bs[64];
    int y = blockIdx.x;
    int b = blockIdx.y;
    int c = threadIdx.x;
    int d = c & 63;
    int h = c >> 6;
    for (int i = c; i < 64 * 25; i += 512) ws[i] = dwc_w[i];
    if (c < 64) bs[c] = dwc_b[c];
    __syncthreads();

    const float* vbase = &d_qgkv[(size_t)(b * Nn) * 1024 + h * 128 + 64 + d];
    const float* gbase = &d_qgkv[(size_t)(b * Nn) * 1024 + h * 128 + d];

    float win[5][5];
#pragma unroll
    for (int dy = 0; dy < 5; dy++) {
        int yy = y + dy - 2;
        bool yok = (unsigned)yy < HW;
#pragma unroll
        for (int j = 0; j < 5; j++) {
            int xx = j - 2;
            win[dy][j] = (yok && (unsigned)xx < HW)
                         ? vbase[(size_t)(yy * HW + xx) * 1024] : 0.f;
        }
    }

    for (int x = 0; x < HW; x++) {
        float acc = bs[d];
#pragma unroll
        for (int dy = 0; dy < 5; dy++)
#pragma unroll
            for (int j = 0; j < 5; j++)
                acc = fmaf(win[dy][j], ws[d * 25 + dy * 5 + j], acc);

        int i1 = b * Nn + y * HW + x;
        float g = gbase[(size_t)(y * HW + x) * 1024];
        size_t pi = perm_h(i1, c);
        float tv = __half2float(d_t[pi]);
        d_t[pi] = __float2half_rn((tv + acc) * g);

        int xx = x + 3;
        bool xok = xx < HW;
#pragma unroll
        for (int dy = 0; dy < 5; dy++) {
#pragma unroll
            for (int j = 0; j < 4; j++) win[dy][j] = win[dy][j + 1];
            int yy = y + dy - 2;
            win[dy][4] = (xok && (unsigned)yy < HW)
                         ? vbase[(size_t)(yy * HW + xx) * 1024] : 0.f;
        }
    }
}

// =====================================================================
// launch (launch #3 == big gemm for ncu capture)
// =====================================================================
extern "C" void kernel_launch(void* const* d_in, const int* in_sizes, int n_in,
                              void* d_out, int out_size)
{
    const float* x       = (const float*)d_in[0];
    const float* qg_w    = (const float*)d_in[1];
    const float* kv_w    = (const float*)d_in[2];
    const float* proj_w  = (const float*)d_in[3];
    const float* proj_b  = (const float*)d_in[4];
    const float* pos_enc = (const float*)d_in[5];
    const float* scale_p = (const float*)d_in[6];
    const float* power_p = (const float*)d_in[7];
    const float* dwc_w   = (const float*)d_in[8];
    const float* dwc_b   = (const float*)d_in[9];
    float* out = (float*)d_out;

    __half *p_t, *p_wtc, *p_wt3, *p_xr;
    float *p_km, *p_kvm;
    cudaGetSymbolAddress((void**)&p_t,    d_t);
    cudaGetSymbolAddress((void**)&p_wtc,  d_wtc);
    cudaGetSymbolAddress((void**)&p_wt3,  d_wt3);
    cudaGetSymbolAddress((void**)&p_xr,   d_xr);
    cudaGetSymbolAddress((void**)&p_km,   d_km);
    cudaGetSymbolAddress((void**)&p_kvm,  d_kvm);

    cudaFuncSetAttribute(gemm_mma, cudaFuncAttributeMaxDynamicSharedMemorySize,
                         GEMM_SMEM);
    cudaFuncSetAttribute(attn_mma, cudaFuncAttributeMaxDynamicSharedMemorySize,
                         ATT_SMEM);

    cudaMemsetAsync(p_km,  0, Bn * NH * Fn * sizeof(float));
    cudaMemsetAsync(p_kvm, 0, Bn * NH * Fn * 64 * sizeof(float));

    dim3 tb(32, 8);
    prep_params<<<1, 512>>>(scale_p, power_p);                       // 0
    permute_x<<<Mrows * 128 / 256, 256>>>(x);                        // 1
    transpose_qgkv<<<dim3(64, 16), tb>>>(qg_w, kv_w);                // 2
    gemm_mma<<<dim3(16, Mrows / 128), 128, GEMM_SMEM>>>(             // 3 (profiled)
        p_xr, p_wtc, nullptr, nullptr, 1024, 1, pos_enc);
    transpose_w<<<dim3(16, 16), tb>>>(proj_w, p_wt3, 512);           // 4
    km_kernel<<<dim3(Bn * NH, 8), Fn>>>();                           // 5
    kvm_mma<<<dim3(Bn * NH, 4), 256>>>();                            // 6
    build_kvm2<<<Bn * NH, 256>>>();                                  // 7
    attn_mma<<<dim3(Nn / 64, Bn * NH), 128, ATT_SMEM>>>();           // 8
    conv_gate_kernel<<<dim3(HW, Bn), 512>>>(dwc_w, dwc_b);           // 9
    gemm_mma<<<dim3(4, Mrows / 128), 128, GEMM_SMEM>>>(              // 10
        p_t, p_wt3, proj_b, out, 512, 0, nullptr);
}